// round 11
// baseline (speedup 1.0000x reference)
#include <cuda_runtime.h>
#include <cuda_bf16.h>
#include <cstdint>
#include <math.h>

typedef long long ll;

#define SQ     2048
#define DIM    2048
#define NHEADS 16
#define NKV    4
#define HDIM   128
#define KVD    512
#define NEXP   8
#define FDIM   2048
#define NTOK   2048

#define BM 128
#define BN 64
#define BK 32
#define LDA2 20
#define LDB2 68
#define SMEM_A_BYTES (BM*LDA2*8)              // 20480
#define SMEM_B_BYTES ((BK/2)*LDB2*8)          // 8704
#define SMEM_BUF     (SMEM_A_BYTES + SMEM_B_BYTES)   // 29184
#define SMEM_BYTES   (2*SMEM_BUF)             // 58368

// flash attention tiles
#define FLASH_LDQ 68                          // Q row stride (uint2)
#define FLASH_LDB 132                         // K/V slice row stride (uint2)
#define FQ_BYTES  (128*FLASH_LDQ*8)           // 69632
#define FKV_BYTES (16*FLASH_LDB*8)            // 16896
#define FLASH_SMEM (FQ_BYTES + 3*FKV_BYTES)   // 120320 (3-buffer ring)

static const float kScaling = 0.08838834764831845f;  // 128^-0.5

// ----------------------------- scratch (device globals) --------------------
__device__ float g_q     [(ll)NTOK*DIM];
__device__ float g_k     [(ll)NTOK*KVD];
__device__ float g_v     [(ll)NTOK*KVD];
__device__ float g_hs2   [(ll)NTOK*DIM];
__device__ float g_t     [(ll)NTOK*DIM];
__device__ float g_gu    [(ll)NTOK*2*FDIM];
__device__ float g_sg    [(ll)NTOK*FDIM];
__device__ float g_su    [(ll)NTOK*FDIM];
__device__ float g_routed[(ll)NTOK*DIM];
__device__ float g_shared[(ll)NTOK*DIM];
// packed split-fp16 (uint2 = {hi_pair, lo_pair} along k)
__device__ uint2 g2_hsn [(ll)NTOK*1024];
__device__ uint2 g2_q   [(ll)NTOK*1024];
__device__ uint2 g2_kT  [(ll)NKV*64*SQ];
__device__ uint2 g2_v   [(ll)1024*KVD];
__device__ uint2 g2_attn[(ll)NTOK*1024];
__device__ uint2 g2_t   [(ll)NTOK*1024];
__device__ uint2 g2_tg  [(ll)NTOK*1024];
__device__ uint2 g2_act [(ll)NTOK*1024];
__device__ uint2 g2_sg  [(ll)NTOK*1024];
__device__ uint2 g2_wq  [(ll)1024*2048];
__device__ uint2 g2_wk  [(ll)1024*512];
__device__ uint2 g2_wv  [(ll)1024*512];
__device__ uint2 g2_wo  [(ll)1024*2048];
__device__ uint2 g2_sgw [(ll)1024*2048];
__device__ uint2 g2_suw [(ll)1024*2048];
__device__ uint2 g2_sdw [(ll)1024*2048];
// router state
__device__ int   g_eidx[NTOK];
__device__ float g_gateval[NTOK];
__device__ int   g_hist[NEXP], g_ctr[NEXP], g_seg_start[NEXP+1], g_seg_count[NEXP];
__device__ int   g_perm[NTOK];

// ----------------------------- helpers -------------------------------------
__device__ __forceinline__ uint32_t smem_u32(const void* p) {
    uint32_t a;
    asm("{ .reg .u64 t; cvta.to.shared.u64 t, %1; cvt.u32.u64 %0, t; }" : "=r"(a) : "l"(p));
    return a;
}
__device__ __forceinline__ uint2 hsplit2(float x, float y) {
    uint2 r;
    asm("{\n\t"
        ".reg .b16 h0,h1,l0,l1;\n\t"
        ".reg .f32 fx,fy;\n\t"
        "cvt.rn.f16.f32 h0, %2;\n\t"
        "cvt.f32.f16 fx, h0;\n\t"
        "sub.f32 fx, %2, fx;\n\t"
        "cvt.rn.f16.f32 l0, fx;\n\t"
        "cvt.rn.f16.f32 h1, %3;\n\t"
        "cvt.f32.f16 fy, h1;\n\t"
        "sub.f32 fy, %3, fy;\n\t"
        "cvt.rn.f16.f32 l1, fy;\n\t"
        "mov.b32 %0, {h0,h1};\n\t"
        "mov.b32 %1, {l0,l1};\n\t"
        "}" : "=r"(r.x), "=r"(r.y) : "f"(x), "f"(y));
    return r;
}
__device__ __forceinline__ void mma_f16(float* c, uint32_t a0, uint32_t a1, uint32_t a2, uint32_t a3,
                                        uint32_t b0, uint32_t b1) {
    asm volatile("mma.sync.aligned.m16n8k16.row.col.f32.f16.f16.f32 "
        "{%0,%1,%2,%3}, {%4,%5,%6,%7}, {%8,%9}, {%0,%1,%2,%3};"
        : "+f"(c[0]), "+f"(c[1]), "+f"(c[2]), "+f"(c[3])
        : "r"(a0), "r"(a1), "r"(a2), "r"(a3), "r"(b0), "r"(b1));
}
__device__ __forceinline__ void cpa16(uint32_t dst, const void* src, int szbytes) {
    asm volatile("cp.async.cg.shared.global [%0], [%1], 16, %2;"
        :: "r"(dst), "l"(src), "r"(szbytes));
}

// ----------------------------- GEMM tile copy helpers -----------------------
__device__ __forceinline__ void issue_A(
    uint32_t sa, const uint2* __restrict__ A,
    int M, int lda2, int m0, int jbase, int tid)
{
#pragma unroll
    for (int i = 0; i < 4; i++) {
        int chunk = tid + (i << 8);
        int row = chunk >> 3, sp = (chunk & 7) << 1;
        int gm = m0 + row;
        int ok = (gm < M) ? 16 : 0;
        const uint2* src = A + (ll)min(gm, M - 1)*lda2 + jbase + sp;
        cpa16(sa + (uint32_t)(row*LDA2 + sp)*8u, src, ok);
    }
}
__device__ __forceinline__ void issue_B(
    uint32_t sb, const uint2* __restrict__ B,
    int ldbN, int n0, int jbase, int tid)
{
#pragma unroll
    for (int i = 0; i < 2; i++) {
        int chunk = tid + (i << 8);
        int jr = chunk >> 5, nq = (chunk & 31) << 1;
        const uint2* src = B + (ll)(jbase + jr)*ldbN + n0 + nq;
        cpa16(sb + (uint32_t)(jr*LDB2 + nq)*8u, src, 16);
    }
}

// ----------------------------- tensor GEMM body -----------------------------
template<bool KCAP, bool RM, bool PACKC, bool BF32>
__device__ __forceinline__ void hm_body(
    const uint2* __restrict__ A, const void* __restrict__ Bv,
    void* __restrict__ Cv, const float* __restrict__ Cadd,
    int M, int K, int lda2, int ldbN, int ldc, int m0, int n0,
    const int* __restrict__ rowmap)
{
    extern __shared__ char smem[];
    const uint32_t sbase = smem_u32(smem);

    const int tid = threadIdx.x;
    const int wid = tid >> 5, lid = tid & 31;
    const int wm = (wid & 3) << 5;
    const int wn = (wid >> 2) << 5;
    const int lr = lid >> 2;
    const int ca = lid & 3;
    const int lc = ca << 1;

    const float* Bf = reinterpret_cast<const float*>(Bv);
    const uint2* Bp = reinterpret_cast<const uint2*>(Bv);
    const int b_kr2 = tid >> 4;
    const int b_n4  = (tid & 15) << 2;
    float4 vb0, vb1;

    float acc[2][4][4];
#pragma unroll
    for (int i = 0; i < 2; i++)
#pragma unroll
        for (int j = 0; j < 4; j++)
#pragma unroll
            for (int q = 0; q < 4; q++) acc[i][j][q] = 0.f;

    int Keff = K;
    if (KCAP) Keff = min(K, m0 + BM);
    const int nch = Keff >> 5;

    issue_A(sbase, A, M, lda2, m0, 0, tid);
    if (!BF32) issue_B(sbase + SMEM_A_BYTES, Bp, ldbN, n0, 0, tid);
    asm volatile("cp.async.commit_group;" ::: "memory");
    if (BF32) {
        const float* bp = Bf + (ll)(2*b_kr2)*ldbN + n0 + b_n4;
        vb0 = *reinterpret_cast<const float4*>(bp);
        vb1 = *reinterpret_cast<const float4*>(bp + ldbN);
    }

    for (int c = 0; c < nch; c++) {
        const int cur = c & 1;
        if (BF32) {
            uint2* Bsw = reinterpret_cast<uint2*>(smem + cur*SMEM_BUF + SMEM_A_BYTES);
            Bsw[b_kr2*LDB2 + b_n4 + 0] = hsplit2(vb0.x, vb1.x);
            Bsw[b_kr2*LDB2 + b_n4 + 1] = hsplit2(vb0.y, vb1.y);
            Bsw[b_kr2*LDB2 + b_n4 + 2] = hsplit2(vb0.z, vb1.z);
            Bsw[b_kr2*LDB2 + b_n4 + 3] = hsplit2(vb0.w, vb1.w);
        }
        if (c + 1 < nch) {
            uint32_t nb = sbase + (uint32_t)(cur ^ 1)*SMEM_BUF;
            issue_A(nb, A, M, lda2, m0, (c + 1) << 4, tid);
            if (!BF32) issue_B(nb + SMEM_A_BYTES, Bp, ldbN, n0, (c + 1) << 4, tid);
            asm volatile("cp.async.commit_group;" ::: "memory");
            if (BF32) {
                const float* bp = Bf + (ll)(((c + 1) << 5) + 2*b_kr2)*ldbN + n0 + b_n4;
                vb0 = *reinterpret_cast<const float4*>(bp);
                vb1 = *reinterpret_cast<const float4*>(bp + ldbN);
            }
            asm volatile("cp.async.wait_group 1;" ::: "memory");
        } else {
            asm volatile("cp.async.wait_group 0;" ::: "memory");
        }
        __syncthreads();

        const uint2* As = reinterpret_cast<const uint2*>(smem + cur*SMEM_BUF);
        const uint2* Bs = reinterpret_cast<const uint2*>(smem + cur*SMEM_BUF + SMEM_A_BYTES);

#pragma unroll
        for (int s = 0; s < 2; s++) {
            const int jb = s << 3;
            uint2 bfr[4][2];
#pragma unroll
            for (int nt = 0; nt < 4; nt++) {
                int n = wn + nt*8 + lr;
                bfr[nt][0] = Bs[(jb + ca    )*LDB2 + n];
                bfr[nt][1] = Bs[(jb + ca + 4)*LDB2 + n];
            }
#pragma unroll
            for (int mt = 0; mt < 2; mt++) {
                int r = wm + mt*16 + lr;
                uint2 a0 = As[ r     *LDA2 + jb + ca    ];
                uint2 a1 = As[(r + 8)*LDA2 + jb + ca    ];
                uint2 a2 = As[ r     *LDA2 + jb + ca + 4];
                uint2 a3 = As[(r + 8)*LDA2 + jb + ca + 4];
#pragma unroll
                for (int nt = 0; nt < 4; nt++) {
                    mma_f16(acc[mt][nt], a0.x, a1.x, a2.x, a3.x, bfr[nt][0].x, bfr[nt][1].x);
                    mma_f16(acc[mt][nt], a0.x, a1.x, a2.x, a3.x, bfr[nt][0].y, bfr[nt][1].y);
                    mma_f16(acc[mt][nt], a0.y, a1.y, a2.y, a3.y, bfr[nt][0].x, bfr[nt][1].x);
                }
            }
        }
        __syncthreads();
    }

#pragma unroll
    for (int mt = 0; mt < 2; mt++) {
        int mbase = m0 + wm + mt*16 + lr;
#pragma unroll
        for (int half = 0; half < 2; half++) {
            int m = mbase + half*8;
            if (m < M) {
                int srow = RM ? rowmap[m] : m;
#pragma unroll
                for (int nt = 0; nt < 4; nt++) {
                    int n = n0 + wn + nt*8 + lc;
                    float2 v = half ? make_float2(acc[mt][nt][2], acc[mt][nt][3])
                                    : make_float2(acc[mt][nt][0], acc[mt][nt][1]);
                    if (PACKC) {
                        uint2* C2 = reinterpret_cast<uint2*>(Cv);
                        C2[(ll)srow*(ldc >> 1) + (n >> 1)] = hsplit2(v.x, v.y);
                    } else {
                        float* C = reinterpret_cast<float*>(Cv);
                        if (Cadd) {
                            float2 a = *reinterpret_cast<const float2*>(Cadd + (ll)m*ldc + n);
                            v.x += a.x; v.y += a.y;
                        }
                        *reinterpret_cast<float2*>(C + (ll)srow*ldc + n) = v;
                    }
                }
            }
        }
    }
}

// ----------------------------- GEMM wrappers -------------------------------
__global__ void __launch_bounds__(256, 3) hm_dense(
    const uint2* __restrict__ A, const uint2* __restrict__ B,
    float* __restrict__ C, const float* __restrict__ Cadd,
    int M, int K, int lda2, int ldbN, int ldc)
{
    hm_body<false, false, false, false>(A, B, C, Cadd, M, K, lda2, ldbN, ldc,
                                        blockIdx.x << 7, blockIdx.y << 6, nullptr);
}

__global__ void __launch_bounds__(256, 3) hm_dense2(
    const uint2* __restrict__ A,
    const uint2* __restrict__ B0, float* __restrict__ C0,
    const uint2* __restrict__ B1, float* __restrict__ C1,
    int M, int K, int lda2, int ldbN, int ldc)
{
    const uint2* B = blockIdx.z ? B1 : B0;
    float* C = blockIdx.z ? C1 : C0;
    hm_body<false, false, false, false>(A, B, C, nullptr, M, K, lda2, ldbN, ldc,
                                        blockIdx.x << 7, blockIdx.y << 6, nullptr);
}

__global__ void __launch_bounds__(256, 2) hm_gateup(
    const uint2* __restrict__ tg2, const float* __restrict__ gup, float* __restrict__ gu)
{
    int e = blockIdx.z;
    int cnt = g_seg_count[e];
    int m0 = blockIdx.x << 7;
    if (m0 >= cnt) return;
    int st = g_seg_start[e];
    hm_body<false, false, false, true>(tg2 + (ll)st*1024, gup + (ll)e*DIM*2*FDIM,
                                       gu + (ll)st*2*FDIM, nullptr,
                                       cnt, DIM, 1024, 2*FDIM, 2*FDIM, m0, blockIdx.y << 6, nullptr);
}

__global__ void __launch_bounds__(256, 2) hm_down(
    const uint2* __restrict__ act2, const float* __restrict__ dwn, float* __restrict__ outr)
{
    int e = blockIdx.z;
    int cnt = g_seg_count[e];
    int m0 = blockIdx.x << 7;
    if (m0 >= cnt) return;
    int st = g_seg_start[e];
    hm_body<false, true, false, true>(act2 + (ll)st*1024, dwn + (ll)e*FDIM*DIM,
                                      outr, nullptr,
                                      cnt, FDIM, 1024, DIM, DIM, m0, blockIdx.y << 6, g_perm + st);
}

// ----------------------------- flash attention ------------------------------
__device__ __forceinline__ void flash_issue(
    uint32_t dstbase, const uint2* __restrict__ src0, ll rowstride, int tid)
{
#pragma unroll
    for (int i = 0; i < 4; i++) {
        int c = tid + (i << 8);
        int jr = c >> 6;
        int sp = (c & 63) << 1;
        cpa16(dstbase + (uint32_t)(jr*FLASH_LDB + sp)*8u, src0 + (ll)jr*rowstride + sp, 16);
    }
    asm volatile("cp.async.commit_group;" ::: "memory");
}

__global__ void __launch_bounds__(256, 1) flash_attn(
    const uint2* __restrict__ q2, const uint2* __restrict__ kT2,
    const uint2* __restrict__ v2, uint2* __restrict__ attn2)
{
    const int h = blockIdx.y;
    const int mtile = 15 - blockIdx.x;      // heavy tiles first
    const int m0 = mtile << 7;
    extern __shared__ char smem[];
    const uint32_t sbase = smem_u32(smem);
    const uint32_t kv0 = sbase + FQ_BYTES;

    const int tid = threadIdx.x, wid = tid >> 5, lid = tid & 31;
    const int wm = wid << 4;                // 16 rows per warp
    const int lr = lid >> 2, ca = lid & 3;

    // Q tile: 128 rows x 64 kpairs, loaded once (commit group #0)
    {
        const uint2* qsrc = q2 + (ll)m0*1024 + h*64;
#pragma unroll
        for (int i = 0; i < 16; i++) {
            int c = tid + (i << 8);
            int row = c >> 5;
            int sp = (c & 31) << 1;
            cpa16(sbase + (uint32_t)(row*FLASH_LDQ + sp)*8u, qsrc + (ll)row*1024 + sp, 16);
        }
        asm volatile("cp.async.commit_group;" ::: "memory");
    }
    const uint2* Kh = kT2 + (ll)(h >> 2)*64*SQ;
    const uint2* Vh = v2 + (h >> 2)*HDIM;
    const uint2* Qw = reinterpret_cast<const uint2*>(smem);

    float oacc[16][4];
#pragma unroll
    for (int nt = 0; nt < 16; nt++)
#pragma unroll
        for (int q = 0; q < 4; q++) oacc[nt][q] = 0.f;
    float mxr0 = -1e30f, mxr1 = -1e30f, l0 = 0.f, l1 = 0.f;
    float sacc[16][4];

    const int total = (mtile + 1) << 3;     // 8 chunks per key-tile

    // ring prologue: chunks 0, 1
    {
        // chunk 0 = K slice 0 of jt 0
        flash_issue(kv0, Kh, SQ, tid);
        // chunk 1 = K slice 1 of jt 0 (total >= 8 always)
        flash_issue(kv0 + FKV_BYTES, Kh + (ll)16*SQ, SQ, tid);
    }

#pragma unroll 1
    for (int g = 0; g < total; g++) {
        if (g == total - 1) {
            asm volatile("cp.async.wait_group 0;" ::: "memory");
        } else {
            asm volatile("cp.async.wait_group 1;" ::: "memory");
        }
        __syncthreads();   // chunk g ready; all warps done with chunk g-1 (buffer (g+2)%3)

        if (g + 2 < total) {
            int gn = g + 2;
            int un = gn & 7, jtn = gn >> 3, s0n = jtn << 7;
            uint32_t dst = kv0 + (uint32_t)(gn % 3)*FKV_BYTES;
            if (un < 4)
                flash_issue(dst, Kh + (ll)(16*un)*SQ + s0n, SQ, tid);
            else
                flash_issue(dst, Vh + (ll)((s0n >> 1) + 16*(un - 4))*512, 512, tid);
        }

        const int u = g & 7, jt = g >> 3;
        const uint2* Bs = reinterpret_cast<const uint2*>(smem + FQ_BYTES + (uint32_t)(g % 3)*FKV_BYTES);

        if (u < 4) {
            // ---- S chunk u: S[:, jt*128 ...] += Q[:, u*32 k] K^T ----
            if (u == 0) {
#pragma unroll
                for (int nt = 0; nt < 16; nt++)
#pragma unroll
                    for (int q = 0; q < 4; q++) sacc[nt][q] = 0.f;
            }
#pragma unroll
            for (int s = 0; s < 2; s++) {
                const int jb = s << 3;
                const int qj = (u << 4) + jb;
                uint2 a0 = Qw[(wm + lr    )*FLASH_LDQ + qj + ca    ];
                uint2 a1 = Qw[(wm + lr + 8)*FLASH_LDQ + qj + ca    ];
                uint2 a2 = Qw[(wm + lr    )*FLASH_LDQ + qj + ca + 4];
                uint2 a3 = Qw[(wm + lr + 8)*FLASH_LDQ + qj + ca + 4];
#pragma unroll
                for (int nt = 0; nt < 16; nt++) {
                    uint2 b0 = Bs[(jb + ca    )*FLASH_LDB + nt*8 + lr];
                    uint2 b1 = Bs[(jb + ca + 4)*FLASH_LDB + nt*8 + lr];
                    mma_f16(sacc[nt], a0.x, a1.x, a2.x, a3.x, b0.x, b1.x);
                    mma_f16(sacc[nt], a0.x, a1.x, a2.x, a3.x, b0.y, b1.y);
                    mma_f16(sacc[nt], a0.y, a1.y, a2.y, a3.y, b0.x, b1.x);
                }
            }
        } else {
            if (u == 4) {
                // ---- online softmax (overlaps in-flight V loads) ----
                if (jt == mtile) {
                    int r0 = wm + lr;
#pragma unroll
                    for (int nt = 0; nt < 16; nt++) {
                        int cb = nt*8 + (ca << 1);
                        if (cb     > r0    ) sacc[nt][0] = -1e30f;
                        if (cb + 1 > r0    ) sacc[nt][1] = -1e30f;
                        if (cb     > r0 + 8) sacc[nt][2] = -1e30f;
                        if (cb + 1 > r0 + 8) sacc[nt][3] = -1e30f;
                    }
                }
                float m0n = -1e30f, m1n = -1e30f;
#pragma unroll
                for (int nt = 0; nt < 16; nt++) {
                    m0n = fmaxf(m0n, fmaxf(sacc[nt][0], sacc[nt][1]));
                    m1n = fmaxf(m1n, fmaxf(sacc[nt][2], sacc[nt][3]));
                }
                m0n = fmaxf(m0n, __shfl_xor_sync(0xffffffffu, m0n, 1));
                m0n = fmaxf(m0n, __shfl_xor_sync(0xffffffffu, m0n, 2));
                m1n = fmaxf(m1n, __shfl_xor_sync(0xffffffffu, m1n, 1));
                m1n = fmaxf(m1n, __shfl_xor_sync(0xffffffffu, m1n, 2));
                float mn0 = fmaxf(mxr0, m0n), mn1 = fmaxf(mxr1, m1n);
                float al0 = expf(mxr0 - mn0), al1 = expf(mxr1 - mn1);
                float su0 = 0.f, su1 = 0.f;
#pragma unroll
                for (int nt = 0; nt < 16; nt++) {
                    float p0 = expf(sacc[nt][0] - mn0);
                    float p1 = expf(sacc[nt][1] - mn0);
                    float p2 = expf(sacc[nt][2] - mn1);
                    float p3 = expf(sacc[nt][3] - mn1);
                    sacc[nt][0] = p0; sacc[nt][1] = p1; sacc[nt][2] = p2; sacc[nt][3] = p3;
                    su0 += p0 + p1; su1 += p2 + p3;
                }
                su0 += __shfl_xor_sync(0xffffffffu, su0, 1);
                su0 += __shfl_xor_sync(0xffffffffu, su0, 2);
                su1 += __shfl_xor_sync(0xffffffffu, su1, 1);
                su1 += __shfl_xor_sync(0xffffffffu, su1, 2);
                l0 = al0*l0 + su0; l1 = al1*l1 + su1;
                mxr0 = mn0; mxr1 = mn1;
#pragma unroll
                for (int nt = 0; nt < 16; nt++) {
                    oacc[nt][0] *= al0; oacc[nt][1] *= al0;
                    oacc[nt][2] *= al1; oacc[nt][3] *= al1;
                }
            }
            // ---- PV chunk u-4: O += P[:, chunk] V[chunk, :] ----
            const int vc = u - 4;
#pragma unroll
            for (int kk = 0; kk < 2; kk++) {
                const int gk = (vc << 1) + kk;
                const int jb = kk << 3;
                uint2 A0 = hsplit2(sacc[2*gk    ][0], sacc[2*gk    ][1]);
                uint2 A1 = hsplit2(sacc[2*gk    ][2], sacc[2*gk    ][3]);
                uint2 A2 = hsplit2(sacc[2*gk + 1][0], sacc[2*gk + 1][1]);
                uint2 A3 = hsplit2(sacc[2*gk + 1][2], sacc[2*gk + 1][3]);
#pragma unroll
                for (int nt = 0; nt < 16; nt++) {
                    uint2 b0 = Bs[(jb + ca    )*FLASH_LDB + nt*8 + lr];
                    uint2 b1 = Bs[(jb + ca + 4)*FLASH_LDB + nt*8 + lr];
                    mma_f16(oacc[nt], A0.x, A1.x, A2.x, A3.x, b0.x, b1.x);
                    mma_f16(oacc[nt], A0.x, A1.x, A2.x, A3.x, b0.y, b1.y);
                    mma_f16(oacc[nt], A0.y, A1.y, A2.y, A3.y, b0.x, b1.x);
                }
            }
        }
    }

    // ---- epilogue: normalize + pack to attn2 (PA layout) ----
    float inv0 = 1.f / l0, inv1 = 1.f / l1;
    int row0 = m0 + wm + lr;
    uint2* d0 = attn2 + (ll)row0*1024 + h*64;
    uint2* d1 = attn2 + (ll)(row0 + 8)*1024 + h*64;
#pragma unroll
    for (int nt = 0; nt < 16; nt++) {
        d0[nt*4 + ca] = hsplit2(oacc[nt][0]*inv0, oacc[nt][1]*inv0);
        d1[nt*4 + ca] = hsplit2(oacc[nt][2]*inv1, oacc[nt][3]*inv1);
    }
}

// ----------------------------- packers / converters -------------------------
__global__ void __launch_bounds__(256) conv_pb4(
    const float* __restrict__ src, uint2* __restrict__ dst, int nlog)
{
    ll i = ((ll)blockIdx.x*256 + threadIdx.x) << 2;
    ll n = i & ((1 << nlog) - 1);
    ll j = i >> nlog;
    const float4 x = *reinterpret_cast<const float4*>(src + ((j << 1)      << nlog) + n);
    const float4 y = *reinterpret_cast<const float4*>(src + (((j << 1)|1)  << nlog) + n);
    uint2 d0 = hsplit2(x.x, y.x);
    uint2 d1 = hsplit2(x.y, y.y);
    uint2 d2 = hsplit2(x.z, y.z);
    uint2 d3 = hsplit2(x.w, y.w);
    uint4* o = reinterpret_cast<uint4*>(dst + i);
    o[0] = make_uint4(d0.x, d0.y, d1.x, d1.y);
    o[1] = make_uint4(d2.x, d2.y, d3.x, d3.y);
}

__global__ void __launch_bounds__(256) rms_pack(
    const float* __restrict__ x, const float* __restrict__ w,
    float* __restrict__ y, uint2* __restrict__ y2)
{
    int row = blockIdx.x, tid = threadIdx.x;
    const float* xr = x + (ll)row*DIM;
    float s = 0.f;
    for (int d = tid; d < DIM; d += 256) { float v = xr[d]; s = fmaf(v, v, s); }
    __shared__ float red[256];
    red[tid] = s; __syncthreads();
    for (int o = 128; o > 0; o >>= 1) { if (tid < o) red[tid] += red[tid+o]; __syncthreads(); }
    float inv = rsqrtf(red[0] * (1.0f/DIM) + 1e-5f);
    for (int d2 = tid; d2 < 1024; d2 += 256) {
        float2 v = *reinterpret_cast<const float2*>(xr + 2*d2);
        float a = v.x * inv * w[2*d2];
        float b = v.y * inv * w[2*d2+1];
        if (y) *reinterpret_cast<float2*>(y + (ll)row*DIM + 2*d2) = make_float2(a, b);
        y2[(ll)row*1024 + d2] = hsplit2(a, b);
    }
}

// RoPE + L2 norm; KM=0: PA out (q2, pre-scaled by kScaling), KM=1: PB-transposed (kT2)
template<int KM>
__global__ void rope_pack(const float* __restrict__ in, const float* __restrict__ cosb,
                          const float* __restrict__ sinb, uint2* __restrict__ out, int ld)
{
    int s = blockIdx.x, h = blockIdx.y, j = threadIdx.x;  // j: 0..63
    const float* p = in + (ll)s*ld + h*HDIM;
    float a = p[2*j], b = p[2*j+1];
    float c  = cosb[s*64 + j];
    float sn = sinb[s*64 + j];
    float na = a*c - b*sn;
    float nb = a*sn + b*c;
    __shared__ float red[64];
    red[j] = na*na + nb*nb; __syncthreads();
    for (int o = 32; o > 0; o >>= 1) { if (j < o) red[j] += red[j+o]; __syncthreads(); }
    float scale = rsqrtf(red[0] * (1.0f/HDIM) + 1e-6f);
    if (KM == 0) scale *= kScaling;
    na *= scale; nb *= scale;
    if (KM == 0)
        out[(ll)s*1024 + h*64 + j] = hsplit2(na, nb);
    else
        out[(ll)(h*64 + j)*SQ + s] = hsplit2(na, nb);
}

__global__ void __launch_bounds__(256) router_kernel(
    const float* __restrict__ t, const float* __restrict__ rw)
{
    int row = blockIdx.x, tid = threadIdx.x;
    float acc[NEXP] = {};
    const float* xr = t + (ll)row*DIM;
    for (int d = tid; d < DIM; d += 256) {
        float x = xr[d];
        const float* r = rw + d*NEXP;
#pragma unroll
        for (int e = 0; e < NEXP; e++) acc[e] = fmaf(x, r[e], acc[e]);
    }
    __shared__ float red[NEXP][256];
#pragma unroll
    for (int e = 0; e < NEXP; e++) red[e][tid] = acc[e];
    __syncthreads();
    for (int o = 128; o > 0; o >>= 1) {
        if (tid < o)
#pragma unroll
            for (int e = 0; e < NEXP; e++) red[e][tid] += red[e][tid+o];
        __syncthreads();
    }
    if (tid == 0) {
        float best = red[0][0]; int bi = 0;
#pragma unroll
        for (int e = 1; e < NEXP; e++) if (red[e][0] > best) { best = red[e][0]; bi = e; }
        g_eidx[row] = bi;
        g_gateval[row] = 1.f / (1.f + expf(-best));
        atomicAdd(&g_hist[bi], 1);
    }
}

__global__ void zero8_kernel() {
    int i = threadIdx.x;
    if (i < NEXP) { g_hist[i] = 0; g_ctr[i] = 0; }
}
__global__ void prefix_kernel() {
    if (threadIdx.x == 0) {
        int s = 0;
        for (int e = 0; e < NEXP; e++) { g_seg_start[e] = s; g_seg_count[e] = g_hist[e]; s += g_hist[e]; }
        g_seg_start[NEXP] = s;
    }
}
__global__ void scatter_kernel() {
    int tk = blockIdx.x*256 + threadIdx.x;
    if (tk < NTOK) {
        int e = g_eidx[tk];
        int pos = atomicAdd(&g_ctr[e], 1);
        g_perm[g_seg_start[e] + pos] = tk;
    }
}

__global__ void __launch_bounds__(256) gather_pack(const float* __restrict__ t) {
    int i = blockIdx.x;
    int s = g_perm[i];
    float g = g_gateval[s];
    const float* src = t + (ll)s*DIM;
    for (int d2 = threadIdx.x; d2 < 1024; d2 += 256) {
        float2 v = *reinterpret_cast<const float2*>(src + 2*d2);
        g2_tg[(ll)i*1024 + d2] = hsplit2(v.x*g, v.y*g);
    }
}

__global__ void __launch_bounds__(256) act_pack(const float* __restrict__ gu) {
    ll i2 = (ll)blockIdx.x*256 + threadIdx.x;
    ll row = i2 >> 10, f2 = i2 & 1023;
    const float* r = gu + row*2*FDIM;
    float g0 = r[2*f2], g1 = r[2*f2+1];
    float u0 = r[FDIM + 2*f2], u1 = r[FDIM + 2*f2+1];
    float a0 = u0 * (g0 / (1.f + expf(-g0)));
    float a1 = u1 * (g1 / (1.f + expf(-g1)));
    g2_act[i2] = hsplit2(a0, a1);
}

__global__ void __launch_bounds__(256) swiglu_pack(
    const float* __restrict__ g, const float* __restrict__ u)
{
    ll i2 = (ll)blockIdx.x*256 + threadIdx.x;
    float g0 = g[2*i2], g1 = g[2*i2+1];
    float u0 = u[2*i2], u1 = u[2*i2+1];
    float a0 = u0 * (g0 / (1.f + expf(-g0)));
    float a1 = u1 * (g1 / (1.f + expf(-g1)));
    g2_sg[i2] = hsplit2(a0, a1);
}

__global__ void __launch_bounds__(256) final_add_kernel(
    const float* __restrict__ hs2, const float* __restrict__ shared_,
    const float* __restrict__ routed, float* __restrict__ out)
{
    ll i = (ll)blockIdx.x*256 + threadIdx.x;
    out[i] = hs2[i] + shared_[i] + routed[i];
}

// ----------------------------- launcher ------------------------------------
static void* symp(const void* sym) { void* p = nullptr; cudaGetSymbolAddress(&p, sym); return p; }

extern "C" void kernel_launch(void* const* d_in, const int* in_sizes, int n_in,
                              void* d_out, int out_size)
{
    (void)in_sizes; (void)n_in; (void)out_size;
    const float* hidden = (const float*)d_in[0];
    const float* fcos   = (const float*)d_in[1];
    const float* fsin   = (const float*)d_in[2];
    const float* wq     = (const float*)d_in[5];
    const float* wk     = (const float*)d_in[6];
    const float* wv     = (const float*)d_in[7];
    const float* wo     = (const float*)d_in[8];
    const float* ln1    = (const float*)d_in[9];
    const float* ln2    = (const float*)d_in[10];
    const float* rw     = (const float*)d_in[11];
    const float* gup    = (const float*)d_in[12];
    const float* dwn    = (const float*)d_in[13];
    const float* sgw    = (const float*)d_in[14];
    const float* suw    = (const float*)d_in[15];
    const float* sdw    = (const float*)d_in[16];
    float* out = (float*)d_out;

    float* qb     = (float*)symp(g_q);
    float* kb     = (float*)symp(g_k);
    float* vb     = (float*)symp(g_v);
    float* hs2    = (float*)symp(g_hs2);
    float* tb     = (float*)symp(g_t);
    float* gu     = (float*)symp(g_gu);
    float* sg     = (float*)symp(g_sg);
    float* su     = (float*)symp(g_su);
    float* routed = (float*)symp(g_routed);
    float* shd    = (float*)symp(g_shared);
    uint2* hsn2   = (uint2*)symp(g2_hsn);
    uint2* q2     = (uint2*)symp(g2_q);
    uint2* kT2    = (uint2*)symp(g2_kT);
    uint2* v2     = (uint2*)symp(g2_v);
    uint2* attn2  = (uint2*)symp(g2_attn);
    uint2* tb2    = (uint2*)symp(g2_t);
    uint2* tg2    = (uint2*)symp(g2_tg);
    uint2* act2   = (uint2*)symp(g2_act);
    uint2* sg2    = (uint2*)symp(g2_sg);
    uint2* wq2    = (uint2*)symp(g2_wq);
    uint2* wk2    = (uint2*)symp(g2_wk);
    uint2* wv2    = (uint2*)symp(g2_wv);
    uint2* wo2    = (uint2*)symp(g2_wo);
    uint2* sgw2   = (uint2*)symp(g2_sgw);
    uint2* suw2   = (uint2*)symp(g2_suw);
    uint2* sdw2   = (uint2*)symp(g2_sdw);

    cudaFuncSetAttribute(hm_dense,   cudaFuncAttributeMaxDynamicSharedMemorySize, SMEM_BYTES);
    cudaFuncSetAttribute(hm_dense2,  cudaFuncAttributeMaxDynamicSharedMemorySize, SMEM_BYTES);
    cudaFuncSetAttribute(hm_gateup,  cudaFuncAttributeMaxDynamicSharedMemorySize, SMEM_BYTES);
    cudaFuncSetAttribute(hm_down,    cudaFuncAttributeMaxDynamicSharedMemorySize, SMEM_BYTES);
    cudaFuncSetAttribute(flash_attn, cudaFuncAttributeMaxDynamicSharedMemorySize, FLASH_SMEM);

    // 0) small-weight conversions (reused 16x by dense GEMMs)
    conv_pb4<<<2048, 256>>>(wq,  wq2,  11);
    conv_pb4<<< 512, 256>>>(wk,  wk2,   9);
    conv_pb4<<< 512, 256>>>(wv,  wv2,   9);
    conv_pb4<<<2048, 256>>>(wo,  wo2,  11);
    conv_pb4<<<2048, 256>>>(sgw, sgw2, 11);
    conv_pb4<<<2048, 256>>>(suw, suw2, 11);
    conv_pb4<<<2048, 256>>>(sdw, sdw2, 11);

    // 1) pre-attn RMSNorm (packed only)
    rms_pack<<<NTOK, 256>>>(hidden, ln1, nullptr, hsn2);
    // 2) QKV projections
    hm_dense <<<dim3(16,32),  256, SMEM_BYTES>>>(hsn2, wq2, qb, nullptr, NTOK, DIM, 1024, 2048, 2048);
    hm_dense2<<<dim3(16,8,2), 256, SMEM_BYTES>>>(hsn2, wk2, kb, wv2, vb, NTOK, DIM, 1024, 512, 512);
    // 3) RoPE + L2 norm -> packed q2 (pre-scaled) / transposed kT2; pack v2
    rope_pack<0><<<dim3(SQ, NHEADS), 64>>>(qb, fcos, fsin, q2, DIM);
    rope_pack<1><<<dim3(SQ, NKV),    64>>>(kb, fcos, fsin, kT2, KVD);
    conv_pb4<<<512, 256>>>(vb, v2, 9);
    // 4-6) fused flash attention (ring-pipelined) -> attn2 (packed)
    flash_attn<<<dim3(16, NHEADS), 256, FLASH_SMEM>>>(q2, kT2, v2, attn2);
    // 7) output proj + residual
    hm_dense<<<dim3(16,32), 256, SMEM_BYTES>>>(attn2, wo2, hs2, hidden, NTOK, DIM, 1024, 2048, 2048);
    // 8) post-attn RMSNorm (fp32 + packed)
    rms_pack<<<NTOK, 256>>>(hs2, ln2, tb, tb2);
    // 9) router
    zero8_kernel<<<1, 32>>>();
    router_kernel<<<NTOK, 256>>>(tb, rw);
    prefix_kernel<<<1, 32>>>();
    scatter_kernel<<<8, 256>>>();
    gather_pack<<<NTOK, 256>>>(tb);
    // 10) routed expert (B fp32, split in-kernel)
    hm_gateup<<<dim3(16,64,NEXP), 256, SMEM_BYTES>>>(tg2, gup, gu);
    act_pack<<<(NTOK*1024)/256, 256>>>(gu);
    hm_down<<<dim3(16,32,NEXP), 256, SMEM_BYTES>>>(act2, dwn, routed);
    // 11) shared expert
    hm_dense2<<<dim3(16,32,2), 256, SMEM_BYTES>>>(tb2, sgw2, sg, suw2, su, NTOK, DIM, 1024, 2048, 2048);
    swiglu_pack<<<(NTOK*1024)/256, 256>>>(sg, su);
    hm_dense<<<dim3(16,32), 256, SMEM_BYTES>>>(sg2, sdw2, shd, nullptr, NTOK, FDIM, 1024, 2048, 2048);
    // 12) final residual + shared + routed
    final_add_kernel<<<(NTOK*DIM)/256, 256>>>(hs2, shd, routed, out);
}

// round 12
// speedup vs baseline: 1.6226x; 1.6226x over previous
#include <cuda_runtime.h>
#include <cuda_bf16.h>
#include <cstdint>
#include <math.h>

typedef long long ll;

#define SQ     2048
#define DIM    2048
#define NHEADS 16
#define NKV    4
#define HDIM   128
#define KVD    512
#define NEXP   8
#define FDIM   2048
#define NTOK   2048

#define BM 128
#define BN 64
#define BK 32
#define LDA2 20
#define LDB2 68
#define SMEM_A_BYTES (BM*LDA2*8)              // 20480
#define SMEM_B_BYTES ((BK/2)*LDB2*8)          // 8704
#define SMEM_BUF     (SMEM_A_BYTES + SMEM_B_BYTES)   // 29184
#define SMEM_BYTES   (2*SMEM_BUF)             // 58368

static const float kScaling = 0.08838834764831845f;  // 128^-0.5

// ----------------------------- scratch (device globals) --------------------
__device__ float g_q     [(ll)NTOK*DIM];
__device__ float g_k     [(ll)NTOK*KVD];
__device__ float g_v     [(ll)NTOK*KVD];
__device__ float g_scores[(ll)NHEADS*SQ*SQ];
__device__ float g_hs2   [(ll)NTOK*DIM];
__device__ float g_t     [(ll)NTOK*DIM];
__device__ float g_gu    [(ll)NTOK*2*FDIM];
__device__ float g_sg    [(ll)NTOK*FDIM];
__device__ float g_su    [(ll)NTOK*FDIM];
__device__ float g_routed[(ll)NTOK*DIM];
__device__ float g_shared[(ll)NTOK*DIM];
// packed split-fp16 (uint2 = {hi_pair, lo_pair} along k)
__device__ uint2 g2_hsn [(ll)NTOK*1024];
__device__ uint2 g2_q   [(ll)NTOK*1024];
__device__ uint2 g2_kT  [(ll)NKV*64*SQ];
__device__ uint2 g2_v   [(ll)1024*KVD];
__device__ uint2 g2_P   [(ll)NHEADS*SQ*1024];
__device__ uint2 g2_attn[(ll)NTOK*1024];
__device__ uint2 g2_t   [(ll)NTOK*1024];
__device__ uint2 g2_tg  [(ll)NTOK*1024];
__device__ uint2 g2_act [(ll)NTOK*1024];
__device__ uint2 g2_sg  [(ll)NTOK*1024];
__device__ uint2 g2_wq  [(ll)1024*2048];
__device__ uint2 g2_wk  [(ll)1024*512];
__device__ uint2 g2_wv  [(ll)1024*512];
__device__ uint2 g2_wo  [(ll)1024*2048];
__device__ uint2 g2_sgw [(ll)1024*2048];
__device__ uint2 g2_suw [(ll)1024*2048];
__device__ uint2 g2_sdw [(ll)1024*2048];
// router state
__device__ int   g_eidx[NTOK];
__device__ float g_gateval[NTOK];
__device__ int   g_hist[NEXP], g_ctr[NEXP], g_seg_start[NEXP+1], g_seg_count[NEXP];
__device__ int   g_perm[NTOK];

// ----------------------------- helpers -------------------------------------
__device__ __forceinline__ uint32_t smem_u32(const void* p) {
    uint32_t a;
    asm("{ .reg .u64 t; cvta.to.shared.u64 t, %1; cvt.u32.u64 %0, t; }" : "=r"(a) : "l"(p));
    return a;
}
// split (x,y) -> {hi_pair, lo_pair} using packed f16x2 converts (same .rn numerics)
__device__ __forceinline__ uint2 hsplit2(float x, float y) {
    uint2 r;
    asm("{\n\t"
        ".reg .b16 hx,hy;\n\t"
        ".reg .f32 fx,fy,rx,ry;\n\t"
        "cvt.rn.f16x2.f32 %0, %3, %2;\n\t"
        "mov.b32 {hx,hy}, %0;\n\t"
        "cvt.f32.f16 fx, hx;\n\t"
        "cvt.f32.f16 fy, hy;\n\t"
        "sub.f32 rx, %2, fx;\n\t"
        "sub.f32 ry, %3, fy;\n\t"
        "cvt.rn.f16x2.f32 %1, ry, rx;\n\t"
        "}" : "=r"(r.x), "=r"(r.y) : "f"(x), "f"(y));
    return r;
}
__device__ __forceinline__ void mma_f16(float* c, uint32_t a0, uint32_t a1, uint32_t a2, uint32_t a3,
                                        uint32_t b0, uint32_t b1) {
    asm volatile("mma.sync.aligned.m16n8k16.row.col.f32.f16.f16.f32 "
        "{%0,%1,%2,%3}, {%4,%5,%6,%7}, {%8,%9}, {%0,%1,%2,%3};"
        : "+f"(c[0]), "+f"(c[1]), "+f"(c[2]), "+f"(c[3])
        : "r"(a0), "r"(a1), "r"(a2), "r"(a3), "r"(b0), "r"(b1));
}
__device__ __forceinline__ void cpa16(uint32_t dst, const void* src, int szbytes) {
    asm volatile("cp.async.cg.shared.global [%0], [%1], 16, %2;"
        :: "r"(dst), "l"(src), "r"(szbytes));
}

// ----------------------------- GEMM tile copy helpers -----------------------
__device__ __forceinline__ void issue_A(
    uint32_t sa, const uint2* __restrict__ A,
    int M, int lda2, int m0, int jbase, int tid)
{
#pragma unroll
    for (int i = 0; i < 4; i++) {
        int chunk = tid + (i << 8);
        int row = chunk >> 3, sp = (chunk & 7) << 1;
        int gm = m0 + row;
        int ok = (gm < M) ? 16 : 0;
        const uint2* src = A + (ll)min(gm, M - 1)*lda2 + jbase + sp;
        cpa16(sa + (uint32_t)(row*LDA2 + sp)*8u, src, ok);
    }
}
__device__ __forceinline__ void issue_B(
    uint32_t sb, const uint2* __restrict__ B,
    int ldbN, int n0, int jbase, int tid)
{
#pragma unroll
    for (int i = 0; i < 2; i++) {
        int chunk = tid + (i << 8);
        int jr = chunk >> 5, nq = (chunk & 31) << 1;
        const uint2* src = B + (ll)(jbase + jr)*ldbN + n0 + nq;
        cpa16(sb + (uint32_t)(jr*LDB2 + nq)*8u, src, 16);
    }
}

// ----------------------------- tensor GEMM body -----------------------------
template<bool KCAP, bool RM, bool PACKC, bool BF32>
__device__ __forceinline__ void hm_body(
    const uint2* __restrict__ A, const void* __restrict__ Bv,
    void* __restrict__ Cv, const float* __restrict__ Cadd,
    int M, int K, int lda2, int ldbN, int ldc, int m0, int n0,
    const int* __restrict__ rowmap)
{
    extern __shared__ char smem[];
    const uint32_t sbase = smem_u32(smem);

    const int tid = threadIdx.x;
    const int wid = tid >> 5, lid = tid & 31;
    const int wm = (wid & 3) << 5;
    const int wn = (wid >> 2) << 5;
    const int lr = lid >> 2;
    const int ca = lid & 3;
    const int lc = ca << 1;

    const float* Bf = reinterpret_cast<const float*>(Bv);
    const uint2* Bp = reinterpret_cast<const uint2*>(Bv);
    const int b_kr2 = tid >> 4;
    const int b_n4  = (tid & 15) << 2;
    float4 vb0, vb1;

    float acc[2][4][4];
#pragma unroll
    for (int i = 0; i < 2; i++)
#pragma unroll
        for (int j = 0; j < 4; j++)
#pragma unroll
            for (int q = 0; q < 4; q++) acc[i][j][q] = 0.f;

    int Keff = K;
    if (KCAP) Keff = min(K, m0 + BM);
    const int nch = Keff >> 5;

    issue_A(sbase, A, M, lda2, m0, 0, tid);
    if (!BF32) issue_B(sbase + SMEM_A_BYTES, Bp, ldbN, n0, 0, tid);
    asm volatile("cp.async.commit_group;" ::: "memory");
    if (BF32) {
        const float* bp = Bf + (ll)(2*b_kr2)*ldbN + n0 + b_n4;
        vb0 = *reinterpret_cast<const float4*>(bp);
        vb1 = *reinterpret_cast<const float4*>(bp + ldbN);
    }

    for (int c = 0; c < nch; c++) {
        const int cur = c & 1;
        if (BF32) {
            uint2* Bsw = reinterpret_cast<uint2*>(smem + cur*SMEM_BUF + SMEM_A_BYTES);
            Bsw[b_kr2*LDB2 + b_n4 + 0] = hsplit2(vb0.x, vb1.x);
            Bsw[b_kr2*LDB2 + b_n4 + 1] = hsplit2(vb0.y, vb1.y);
            Bsw[b_kr2*LDB2 + b_n4 + 2] = hsplit2(vb0.z, vb1.z);
            Bsw[b_kr2*LDB2 + b_n4 + 3] = hsplit2(vb0.w, vb1.w);
        }
        if (c + 1 < nch) {
            uint32_t nb = sbase + (uint32_t)(cur ^ 1)*SMEM_BUF;
            issue_A(nb, A, M, lda2, m0, (c + 1) << 4, tid);
            if (!BF32) issue_B(nb + SMEM_A_BYTES, Bp, ldbN, n0, (c + 1) << 4, tid);
            asm volatile("cp.async.commit_group;" ::: "memory");
            if (BF32) {
                const float* bp = Bf + (ll)(((c + 1) << 5) + 2*b_kr2)*ldbN + n0 + b_n4;
                vb0 = *reinterpret_cast<const float4*>(bp);
                vb1 = *reinterpret_cast<const float4*>(bp + ldbN);
            }
            asm volatile("cp.async.wait_group 1;" ::: "memory");
        } else {
            asm volatile("cp.async.wait_group 0;" ::: "memory");
        }
        __syncthreads();

        const uint2* As = reinterpret_cast<const uint2*>(smem + cur*SMEM_BUF);
        const uint2* Bs = reinterpret_cast<const uint2*>(smem + cur*SMEM_BUF + SMEM_A_BYTES);

#pragma unroll
        for (int s = 0; s < 2; s++) {
            const int jb = s << 3;
            uint2 bfr[4][2];
#pragma unroll
            for (int nt = 0; nt < 4; nt++) {
                int n = wn + nt*8 + lr;
                bfr[nt][0] = Bs[(jb + ca    )*LDB2 + n];
                bfr[nt][1] = Bs[(jb + ca + 4)*LDB2 + n];
            }
#pragma unroll
            for (int mt = 0; mt < 2; mt++) {
                int r = wm + mt*16 + lr;
                uint2 a0 = As[ r     *LDA2 + jb + ca    ];
                uint2 a1 = As[(r + 8)*LDA2 + jb + ca    ];
                uint2 a2 = As[ r     *LDA2 + jb + ca + 4];
                uint2 a3 = As[(r + 8)*LDA2 + jb + ca + 4];
#pragma unroll
                for (int nt = 0; nt < 4; nt++) {
                    mma_f16(acc[mt][nt], a0.x, a1.x, a2.x, a3.x, bfr[nt][0].x, bfr[nt][1].x);
                    mma_f16(acc[mt][nt], a0.x, a1.x, a2.x, a3.x, bfr[nt][0].y, bfr[nt][1].y);
                    mma_f16(acc[mt][nt], a0.y, a1.y, a2.y, a3.y, bfr[nt][0].x, bfr[nt][1].x);
                }
            }
        }
        __syncthreads();
    }

#pragma unroll
    for (int mt = 0; mt < 2; mt++) {
        int mbase = m0 + wm + mt*16 + lr;
#pragma unroll
        for (int half = 0; half < 2; half++) {
            int m = mbase + half*8;
            if (m < M) {
                int srow = RM ? rowmap[m] : m;
#pragma unroll
                for (int nt = 0; nt < 4; nt++) {
                    int n = n0 + wn + nt*8 + lc;
                    float2 v = half ? make_float2(acc[mt][nt][2], acc[mt][nt][3])
                                    : make_float2(acc[mt][nt][0], acc[mt][nt][1]);
                    if (PACKC) {
                        uint2* C2 = reinterpret_cast<uint2*>(Cv);
                        C2[(ll)srow*(ldc >> 1) + (n >> 1)] = hsplit2(v.x, v.y);
                    } else {
                        float* C = reinterpret_cast<float*>(Cv);
                        if (Cadd) {
                            float2 a = *reinterpret_cast<const float2*>(Cadd + (ll)m*ldc + n);
                            v.x += a.x; v.y += a.y;
                        }
                        *reinterpret_cast<float2*>(C + (ll)srow*ldc + n) = v;
                    }
                }
            }
        }
    }
}

// ----------------------------- GEMM wrappers -------------------------------
__global__ void __launch_bounds__(256, 3) hm_dense(
    const uint2* __restrict__ A, const uint2* __restrict__ B,
    float* __restrict__ C, const float* __restrict__ Cadd,
    int M, int K, int lda2, int ldbN, int ldc)
{
    hm_body<false, false, false, false>(A, B, C, Cadd, M, K, lda2, ldbN, ldc,
                                        blockIdx.x << 7, blockIdx.y << 6, nullptr);
}

__global__ void __launch_bounds__(256, 3) hm_dense2(
    const uint2* __restrict__ A,
    const uint2* __restrict__ B0, float* __restrict__ C0,
    const uint2* __restrict__ B1, float* __restrict__ C1,
    int M, int K, int lda2, int ldbN, int ldc)
{
    const uint2* B = blockIdx.z ? B1 : B0;
    float* C = blockIdx.z ? C1 : C0;
    hm_body<false, false, false, false>(A, B, C, nullptr, M, K, lda2, ldbN, ldc,
                                        blockIdx.x << 7, blockIdx.y << 6, nullptr);
}

__global__ void __launch_bounds__(256, 3) hm_qk(
    const uint2* __restrict__ q2, const uint2* __restrict__ kT2, float* __restrict__ scv)
{
    int h = blockIdx.z;
    int m0 = blockIdx.x << 7, n0 = blockIdx.y << 6;
    if (n0 > m0 + (BM - 1)) return;
    hm_body<false, false, false, false>(q2 + h*64, kT2 + (ll)(h >> 2)*64*SQ,
                                        scv + (ll)h*SQ*SQ, nullptr,
                                        SQ, HDIM, 1024, SQ, SQ, m0, n0, nullptr);
}

__global__ void __launch_bounds__(256, 3) hm_pv(
    const uint2* __restrict__ P2, const uint2* __restrict__ v2, uint2* __restrict__ attn2)
{
    int h = blockIdx.z;
    hm_body<true, false, true, false>(P2 + (ll)h*SQ*1024, v2 + (h >> 2)*HDIM,
                                      attn2 + h*(HDIM/2), nullptr,
                                      SQ, SQ, 1024, KVD, DIM, blockIdx.x << 7, blockIdx.y << 6, nullptr);
}

__global__ void __launch_bounds__(256, 2) hm_gateup(
    const uint2* __restrict__ tg2, const float* __restrict__ gup, float* __restrict__ gu)
{
    int e = blockIdx.z;
    int cnt = g_seg_count[e];
    int m0 = blockIdx.x << 7;
    if (m0 >= cnt) return;
    int st = g_seg_start[e];
    hm_body<false, false, false, true>(tg2 + (ll)st*1024, gup + (ll)e*DIM*2*FDIM,
                                       gu + (ll)st*2*FDIM, nullptr,
                                       cnt, DIM, 1024, 2*FDIM, 2*FDIM, m0, blockIdx.y << 6, nullptr);
}

__global__ void __launch_bounds__(256, 2) hm_down(
    const uint2* __restrict__ act2, const float* __restrict__ dwn, float* __restrict__ outr)
{
    int e = blockIdx.z;
    int cnt = g_seg_count[e];
    int m0 = blockIdx.x << 7;
    if (m0 >= cnt) return;
    int st = g_seg_start[e];
    hm_body<false, true, false, true>(act2 + (ll)st*1024, dwn + (ll)e*FDIM*DIM,
                                      outr, nullptr,
                                      cnt, FDIM, 1024, DIM, DIM, m0, blockIdx.y << 6, g_perm + st);
}

// ----------------------------- packers / converters -------------------------
__global__ void __launch_bounds__(256) conv_pb4(
    const float* __restrict__ src, uint2* __restrict__ dst, int nlog)
{
    ll i = ((ll)blockIdx.x*256 + threadIdx.x) << 2;
    ll n = i & ((1 << nlog) - 1);
    ll j = i >> nlog;
    const float4 x = *reinterpret_cast<const float4*>(src + ((j << 1)      << nlog) + n);
    const float4 y = *reinterpret_cast<const float4*>(src + (((j << 1)|1)  << nlog) + n);
    uint2 d0 = hsplit2(x.x, y.x);
    uint2 d1 = hsplit2(x.y, y.y);
    uint2 d2 = hsplit2(x.z, y.z);
    uint2 d3 = hsplit2(x.w, y.w);
    uint4* o = reinterpret_cast<uint4*>(dst + i);
    o[0] = make_uint4(d0.x, d0.y, d1.x, d1.y);
    o[1] = make_uint4(d2.x, d2.y, d3.x, d3.y);
}

__global__ void __launch_bounds__(256) rms_pack(
    const float* __restrict__ x, const float* __restrict__ w,
    float* __restrict__ y, uint2* __restrict__ y2)
{
    int row = blockIdx.x, tid = threadIdx.x;
    const float* xr = x + (ll)row*DIM;
    float s = 0.f;
    for (int d = tid; d < DIM; d += 256) { float v = xr[d]; s = fmaf(v, v, s); }
    __shared__ float red[256];
    red[tid] = s; __syncthreads();
    for (int o = 128; o > 0; o >>= 1) { if (tid < o) red[tid] += red[tid+o]; __syncthreads(); }
    float inv = rsqrtf(red[0] * (1.0f/DIM) + 1e-5f);
    for (int d2 = tid; d2 < 1024; d2 += 256) {
        float2 v = *reinterpret_cast<const float2*>(xr + 2*d2);
        float a = v.x * inv * w[2*d2];
        float b = v.y * inv * w[2*d2+1];
        if (y) *reinterpret_cast<float2*>(y + (ll)row*DIM + 2*d2) = make_float2(a, b);
        y2[(ll)row*1024 + d2] = hsplit2(a, b);
    }
}

// RoPE + L2 norm; KM=0: PA out (q2), KM=1: PB-transposed out (kT2)
template<int KM>
__global__ void rope_pack(const float* __restrict__ in, const float* __restrict__ cosb,
                          const float* __restrict__ sinb, uint2* __restrict__ out, int ld)
{
    int s = blockIdx.x, h = blockIdx.y, j = threadIdx.x;  // j: 0..63
    const float* p = in + (ll)s*ld + h*HDIM;
    float a = p[2*j], b = p[2*j+1];
    float c  = cosb[s*64 + j];
    float sn = sinb[s*64 + j];
    float na = a*c - b*sn;
    float nb = a*sn + b*c;
    __shared__ float red[64];
    red[j] = na*na + nb*nb; __syncthreads();
    for (int o = 32; o > 0; o >>= 1) { if (j < o) red[j] += red[j+o]; __syncthreads(); }
    float scale = rsqrtf(red[0] * (1.0f/HDIM) + 1e-6f);
    na *= scale; nb *= scale;
    if (KM == 0)
        out[(ll)s*1024 + h*64 + j] = hsplit2(na, nb);
    else
        out[(ll)(h*64 + j)*SQ + s] = hsplit2(na, nb);
}

// causal softmax -> packed PA P2; single global read pass (rows cached in regs)
__global__ void __launch_bounds__(256) softmax_pack(
    const float* __restrict__ scores, uint2* __restrict__ P2)
{
    int row = blockIdx.x, h = blockIdx.y, tid = threadIdx.x;
    const float* p = scores + ((ll)h*SQ + row)*SQ;
    uint2* o = P2 + ((ll)h*SQ + row)*1024;
    int n = row + 1;
    int np = (n + 1) >> 1;
    int zend2 = ((row >> 7) << 6) + 64;
    __shared__ float red[256];

    float2 xv[4];
    float mx = -1e30f;
#pragma unroll
    for (int k = 0; k < 4; k++) {
        int j2 = tid + (k << 8);
        float2 v = make_float2(-1e30f, -1e30f);
        if (j2 < np) {
            v = *reinterpret_cast<const float2*>(p + 2*j2);
            v.x *= kScaling;
            v.y = (2*j2 + 1 < n) ? v.y * kScaling : -1e30f;
        }
        xv[k] = v;
        mx = fmaxf(mx, fmaxf(v.x, v.y));
    }
    red[tid] = mx; __syncthreads();
    for (int q = 128; q > 0; q >>= 1) { if (tid < q) red[tid] = fmaxf(red[tid], red[tid+q]); __syncthreads(); }
    mx = red[0]; __syncthreads();

    float sum = 0.f;
#pragma unroll
    for (int k = 0; k < 4; k++) {
        int j2 = tid + (k << 8);
        float e0 = expf(xv[k].x - mx);
        float e1 = expf(xv[k].y - mx);
        xv[k] = make_float2(e0, e1);
        if (j2 < np) sum += e0 + e1;
    }
    red[tid] = sum; __syncthreads();
    for (int q = 128; q > 0; q >>= 1) { if (tid < q) red[tid] += red[tid+q]; __syncthreads(); }
    float inv = 1.f / red[0];

#pragma unroll
    for (int k = 0; k < 4; k++) {
        int j2 = tid + (k << 8);
        if (j2 < np) o[j2] = hsplit2(xv[k].x*inv, xv[k].y*inv);
    }
    for (int j2 = np + tid; j2 < zend2; j2 += 256) o[j2] = make_uint2(0u, 0u);
}

__global__ void __launch_bounds__(256) router_kernel(
    const float* __restrict__ t, const float* __restrict__ rw)
{
    int row = blockIdx.x, tid = threadIdx.x;
    float acc[NEXP] = {};
    const float* xr = t + (ll)row*DIM;
    for (int d = tid; d < DIM; d += 256) {
        float x = xr[d];
        const float* r = rw + d*NEXP;
#pragma unroll
        for (int e = 0; e < NEXP; e++) acc[e] = fmaf(x, r[e], acc[e]);
    }
    __shared__ float red[NEXP][256];
#pragma unroll
    for (int e = 0; e < NEXP; e++) red[e][tid] = acc[e];
    __syncthreads();
    for (int o = 128; o > 0; o >>= 1) {
        if (tid < o)
#pragma unroll
            for (int e = 0; e < NEXP; e++) red[e][tid] += red[e][tid+o];
        __syncthreads();
    }
    if (tid == 0) {
        float best = red[0][0]; int bi = 0;
#pragma unroll
        for (int e = 1; e < NEXP; e++) if (red[e][0] > best) { best = red[e][0]; bi = e; }
        g_eidx[row] = bi;
        g_gateval[row] = 1.f / (1.f + expf(-best));
        atomicAdd(&g_hist[bi], 1);
    }
}

__global__ void zero8_kernel() {
    int i = threadIdx.x;
    if (i < NEXP) { g_hist[i] = 0; g_ctr[i] = 0; }
}
__global__ void prefix_kernel() {
    if (threadIdx.x == 0) {
        int s = 0;
        for (int e = 0; e < NEXP; e++) { g_seg_start[e] = s; g_seg_count[e] = g_hist[e]; s += g_hist[e]; }
        g_seg_start[NEXP] = s;
    }
}
__global__ void scatter_kernel() {
    int tk = blockIdx.x*256 + threadIdx.x;
    if (tk < NTOK) {
        int e = g_eidx[tk];
        int pos = atomicAdd(&g_ctr[e], 1);
        g_perm[g_seg_start[e] + pos] = tk;
    }
}

__global__ void __launch_bounds__(256) gather_pack(const float* __restrict__ t) {
    int i = blockIdx.x;
    int s = g_perm[i];
    float g = g_gateval[s];
    const float* src = t + (ll)s*DIM;
    for (int d2 = threadIdx.x; d2 < 1024; d2 += 256) {
        float2 v = *reinterpret_cast<const float2*>(src + 2*d2);
        g2_tg[(ll)i*1024 + d2] = hsplit2(v.x*g, v.y*g);
    }
}

__global__ void __launch_bounds__(256) act_pack(const float* __restrict__ gu) {
    ll i2 = (ll)blockIdx.x*256 + threadIdx.x;
    ll row = i2 >> 10, f2 = i2 & 1023;
    const float* r = gu + row*2*FDIM;
    float g0 = r[2*f2], g1 = r[2*f2+1];
    float u0 = r[FDIM + 2*f2], u1 = r[FDIM + 2*f2+1];
    float a0 = u0 * (g0 / (1.f + expf(-g0)));
    float a1 = u1 * (g1 / (1.f + expf(-g1)));
    g2_act[i2] = hsplit2(a0, a1);
}

__global__ void __launch_bounds__(256) swiglu_pack(
    const float* __restrict__ g, const float* __restrict__ u)
{
    ll i2 = (ll)blockIdx.x*256 + threadIdx.x;
    float g0 = g[2*i2], g1 = g[2*i2+1];
    float u0 = u[2*i2], u1 = u[2*i2+1];
    float a0 = u0 * (g0 / (1.f + expf(-g0)));
    float a1 = u1 * (g1 / (1.f + expf(-g1)));
    g2_sg[i2] = hsplit2(a0, a1);
}

__global__ void __launch_bounds__(256) final_add_kernel(
    const float* __restrict__ hs2, const float* __restrict__ shared_,
    const float* __restrict__ routed, float* __restrict__ out)
{
    ll i = (ll)blockIdx.x*256 + threadIdx.x;
    out[i] = hs2[i] + shared_[i] + routed[i];
}

// ----------------------------- launcher ------------------------------------
static void* symp(const void* sym) { void* p = nullptr; cudaGetSymbolAddress(&p, sym); return p; }

extern "C" void kernel_launch(void* const* d_in, const int* in_sizes, int n_in,
                              void* d_out, int out_size)
{
    (void)in_sizes; (void)n_in; (void)out_size;
    const float* hidden = (const float*)d_in[0];
    const float* fcos   = (const float*)d_in[1];
    const float* fsin   = (const float*)d_in[2];
    const float* wq     = (const float*)d_in[5];
    const float* wk     = (const float*)d_in[6];
    const float* wv     = (const float*)d_in[7];
    const float* wo     = (const float*)d_in[8];
    const float* ln1    = (const float*)d_in[9];
    const float* ln2    = (const float*)d_in[10];
    const float* rw     = (const float*)d_in[11];
    const float* gup    = (const float*)d_in[12];
    const float* dwn    = (const float*)d_in[13];
    const float* sgw    = (const float*)d_in[14];
    const float* suw    = (const float*)d_in[15];
    const float* sdw    = (const float*)d_in[16];
    float* out = (float*)d_out;

    float* qb     = (float*)symp(g_q);
    float* kb     = (float*)symp(g_k);
    float* vb     = (float*)symp(g_v);
    float* sc     = (float*)symp(g_scores);
    float* hs2    = (float*)symp(g_hs2);
    float* tb     = (float*)symp(g_t);
    float* gu     = (float*)symp(g_gu);
    float* sg     = (float*)symp(g_sg);
    float* su     = (float*)symp(g_su);
    float* routed = (float*)symp(g_routed);
    float* shd    = (float*)symp(g_shared);
    uint2* hsn2   = (uint2*)symp(g2_hsn);
    uint2* q2     = (uint2*)symp(g2_q);
    uint2* kT2    = (uint2*)symp(g2_kT);
    uint2* v2     = (uint2*)symp(g2_v);
    uint2* P2     = (uint2*)symp(g2_P);
    uint2* attn2  = (uint2*)symp(g2_attn);
    uint2* tb2    = (uint2*)symp(g2_t);
    uint2* tg2    = (uint2*)symp(g2_tg);
    uint2* act2   = (uint2*)symp(g2_act);
    uint2* sg2    = (uint2*)symp(g2_sg);
    uint2* wq2    = (uint2*)symp(g2_wq);
    uint2* wk2    = (uint2*)symp(g2_wk);
    uint2* wv2    = (uint2*)symp(g2_wv);
    uint2* wo2    = (uint2*)symp(g2_wo);
    uint2* sgw2   = (uint2*)symp(g2_sgw);
    uint2* suw2   = (uint2*)symp(g2_suw);
    uint2* sdw2   = (uint2*)symp(g2_sdw);

    cudaFuncSetAttribute(hm_dense,  cudaFuncAttributeMaxDynamicSharedMemorySize, SMEM_BYTES);
    cudaFuncSetAttribute(hm_dense2, cudaFuncAttributeMaxDynamicSharedMemorySize, SMEM_BYTES);
    cudaFuncSetAttribute(hm_qk,     cudaFuncAttributeMaxDynamicSharedMemorySize, SMEM_BYTES);
    cudaFuncSetAttribute(hm_pv,     cudaFuncAttributeMaxDynamicSharedMemorySize, SMEM_BYTES);
    cudaFuncSetAttribute(hm_gateup, cudaFuncAttributeMaxDynamicSharedMemorySize, SMEM_BYTES);
    cudaFuncSetAttribute(hm_down,   cudaFuncAttributeMaxDynamicSharedMemorySize, SMEM_BYTES);

    // 0) small-weight conversions (reused 16x by dense GEMMs)
    conv_pb4<<<2048, 256>>>(wq,  wq2,  11);
    conv_pb4<<< 512, 256>>>(wk,  wk2,   9);
    conv_pb4<<< 512, 256>>>(wv,  wv2,   9);
    conv_pb4<<<2048, 256>>>(wo,  wo2,  11);
    conv_pb4<<<2048, 256>>>(sgw, sgw2, 11);
    conv_pb4<<<2048, 256>>>(suw, suw2, 11);
    conv_pb4<<<2048, 256>>>(sdw, sdw2, 11);

    // 1) pre-attn RMSNorm (packed only)
    rms_pack<<<NTOK, 256>>>(hidden, ln1, nullptr, hsn2);
    // 2) QKV projections
    hm_dense <<<dim3(16,32),  256, SMEM_BYTES>>>(hsn2, wq2, qb, nullptr, NTOK, DIM, 1024, 2048, 2048);
    hm_dense2<<<dim3(16,8,2), 256, SMEM_BYTES>>>(hsn2, wk2, kb, wv2, vb, NTOK, DIM, 1024, 512, 512);
    // 3) RoPE + L2 norm -> packed q2 / transposed kT2; pack v2
    rope_pack<0><<<dim3(SQ, NHEADS), 64>>>(qb, fcos, fsin, q2, DIM);
    rope_pack<1><<<dim3(SQ, NKV),    64>>>(kb, fcos, fsin, kT2, KVD);
    conv_pb4<<<512, 256>>>(vb, v2, 9);
    // 4) scores = Q K^T (causal tile skip)
    hm_qk<<<dim3(16,32,NHEADS), 256, SMEM_BYTES>>>(q2, kT2, sc);
    // 5) causal softmax -> packed P2 (single-pass)
    softmax_pack<<<dim3(SQ, NHEADS), 256>>>(sc, P2);
    // 6) attn = P V (K capped), packed epilogue
    hm_pv<<<dim3(16,2,NHEADS), 256, SMEM_BYTES>>>(P2, v2, attn2);
    // 7) output proj + residual
    hm_dense<<<dim3(16,32), 256, SMEM_BYTES>>>(attn2, wo2, hs2, hidden, NTOK, DIM, 1024, 2048, 2048);
    // 8) post-attn RMSNorm (fp32 + packed)
    rms_pack<<<NTOK, 256>>>(hs2, ln2, tb, tb2);
    // 9) router
    zero8_kernel<<<1, 32>>>();
    router_kernel<<<NTOK, 256>>>(tb, rw);
    prefix_kernel<<<1, 32>>>();
    scatter_kernel<<<8, 256>>>();
    gather_pack<<<NTOK, 256>>>(tb);
    // 10) routed expert (B fp32, split in-kernel)
    hm_gateup<<<dim3(16,64,NEXP), 256, SMEM_BYTES>>>(tg2, gup, gu);
    act_pack<<<(NTOK*1024)/256, 256>>>(gu);
    hm_down<<<dim3(16,32,NEXP), 256, SMEM_BYTES>>>(act2, dwn, routed);
    // 11) shared expert
    hm_dense2<<<dim3(16,32,2), 256, SMEM_BYTES>>>(tb2, sgw2, sg, suw2, su, NTOK, DIM, 1024, 2048, 2048);
    swiglu_pack<<<(NTOK*1024)/256, 256>>>(sg, su);
    hm_dense<<<dim3(16,32), 256, SMEM_BYTES>>>(sg2, sdw2, shd, nullptr, NTOK, FDIM, 1024, 2048, 2048);
    // 12) final residual + shared + routed
    final_add_kernel<<<(NTOK*DIM)/256, 256>>>(hs2, shd, routed, out);
}

// round 14
// speedup vs baseline: 1.8876x; 1.1634x over previous
#include <cuda_runtime.h>
#include <cuda_bf16.h>
#include <cstdint>
#include <math.h>

typedef long long ll;

#define SQ     2048
#define DIM    2048
#define NHEADS 16
#define NKV    4
#define HDIM   128
#define KVD    512
#define NEXP   8
#define FDIM   2048
#define NTOK   2048

#define BM 128
#define BN 64
#define BK 32
#define LDA2 20
#define LDB2 68
#define SMEM_A_BYTES (BM*LDA2*8)              // 20480
#define SMEM_B_BYTES ((BK/2)*LDB2*8)          // 8704
#define SMEM_BUF     (SMEM_A_BYTES + SMEM_B_BYTES)   // 29184
#define SMEM_BYTES   (2*SMEM_BUF)             // 58368

static const float kScaling = 0.08838834764831845f;  // 128^-0.5

// ----------------------------- scratch (device globals) --------------------
__device__ float g_q     [(ll)NTOK*DIM];
__device__ float g_k     [(ll)NTOK*KVD];
__device__ float g_v     [(ll)NTOK*KVD];
__device__ float g_scores[(ll)NHEADS*SQ*SQ];
__device__ float g_hs2   [(ll)NTOK*DIM];
__device__ float g_t     [(ll)NTOK*DIM];
__device__ float g_gu    [(ll)NTOK*2*FDIM];
__device__ float g_sg    [(ll)NTOK*FDIM];
__device__ float g_su    [(ll)NTOK*FDIM];
__device__ float g_routed[(ll)NTOK*DIM];
__device__ float g_shared[(ll)NTOK*DIM];
// packed split-fp16 (uint2 = {hi_pair, lo_pair} along k)
__device__ uint2 g2_hsn [(ll)NTOK*1024];
__device__ uint2 g2_q   [(ll)NTOK*1024];
__device__ uint2 g2_kT  [(ll)NKV*64*SQ];
__device__ uint2 g2_v   [(ll)1024*KVD];
__device__ uint2 g2_P   [(ll)NHEADS*SQ*1024];
__device__ uint2 g2_attn[(ll)NTOK*1024];
__device__ uint2 g2_t   [(ll)NTOK*1024];
__device__ uint2 g2_tg  [(ll)NTOK*1024];
__device__ uint2 g2_act [(ll)NTOK*1024];
__device__ uint2 g2_sg  [(ll)NTOK*1024];
__device__ uint2 g2_wq  [(ll)1024*2048];
__device__ uint2 g2_wk  [(ll)1024*512];
__device__ uint2 g2_wv  [(ll)1024*512];
__device__ uint2 g2_wo  [(ll)1024*2048];
__device__ uint2 g2_sgw [(ll)1024*2048];
__device__ uint2 g2_suw [(ll)1024*2048];
__device__ uint2 g2_sdw [(ll)1024*2048];
// router state
__device__ int   g_eidx[NTOK];
__device__ float g_gateval[NTOK];
__device__ int   g_hist[NEXP], g_ctr[NEXP], g_seg_start[NEXP+1], g_seg_count[NEXP];
__device__ int   g_perm[NTOK];

// ----------------------------- helpers -------------------------------------
__device__ __forceinline__ uint32_t smem_u32(const void* p) {
    uint32_t a;
    asm("{ .reg .u64 t; cvta.to.shared.u64 t, %1; cvt.u32.u64 %0, t; }" : "=r"(a) : "l"(p));
    return a;
}
// split (x,y) -> {hi_pair, lo_pair}
__device__ __forceinline__ uint2 hsplit2(float x, float y) {
    uint2 r;
    asm("{\n\t"
        ".reg .b16 hx,hy;\n\t"
        ".reg .f32 fx,fy,rx,ry;\n\t"
        "cvt.rn.f16x2.f32 %0, %3, %2;\n\t"
        "mov.b32 {hx,hy}, %0;\n\t"
        "cvt.f32.f16 fx, hx;\n\t"
        "cvt.f32.f16 fy, hy;\n\t"
        "sub.f32 rx, %2, fx;\n\t"
        "sub.f32 ry, %3, fy;\n\t"
        "cvt.rn.f16x2.f32 %1, ry, rx;\n\t"
        "}" : "=r"(r.x), "=r"(r.y) : "f"(x), "f"(y));
    return r;
}
// hi-only pack (for 2-term B): one packed convert
__device__ __forceinline__ uint32_t hpack2(float x, float y) {
    uint32_t r;
    asm("cvt.rn.f16x2.f32 %0, %2, %1;" : "=r"(r) : "f"(x), "f"(y));
    return r;
}
__device__ __forceinline__ void mma_f16(float* c, uint32_t a0, uint32_t a1, uint32_t a2, uint32_t a3,
                                        uint32_t b0, uint32_t b1) {
    asm volatile("mma.sync.aligned.m16n8k16.row.col.f32.f16.f16.f32 "
        "{%0,%1,%2,%3}, {%4,%5,%6,%7}, {%8,%9}, {%0,%1,%2,%3};"
        : "+f"(c[0]), "+f"(c[1]), "+f"(c[2]), "+f"(c[3])
        : "r"(a0), "r"(a1), "r"(a2), "r"(a3), "r"(b0), "r"(b1));
}
__device__ __forceinline__ void cpa16(uint32_t dst, const void* src, int szbytes) {
    asm volatile("cp.async.cg.shared.global [%0], [%1], 16, %2;"
        :: "r"(dst), "l"(src), "r"(szbytes));
}

// ----------------------------- GEMM tile copy helpers -----------------------
__device__ __forceinline__ void issue_A(
    uint32_t sa, const uint2* __restrict__ A,
    int M, int lda2, int m0, int jbase, int tid)
{
#pragma unroll
    for (int i = 0; i < 4; i++) {
        int chunk = tid + (i << 8);
        int row = chunk >> 3, sp = (chunk & 7) << 1;
        int gm = m0 + row;
        int ok = (gm < M) ? 16 : 0;
        const uint2* src = A + (ll)min(gm, M - 1)*lda2 + jbase + sp;
        cpa16(sa + (uint32_t)(row*LDA2 + sp)*8u, src, ok);
    }
}
__device__ __forceinline__ void issue_B(
    uint32_t sb, const uint2* __restrict__ B,
    int ldbN, int n0, int jbase, int tid)
{
#pragma unroll
    for (int i = 0; i < 2; i++) {
        int chunk = tid + (i << 8);
        int jr = chunk >> 5, nq = (chunk & 31) << 1;
        const uint2* src = B + (ll)(jbase + jr)*ldbN + n0 + nq;
        cpa16(sb + (uint32_t)(jr*LDB2 + nq)*8u, src, 16);
    }
}

// ----------------------------- tensor GEMM body -----------------------------
// NT=3: Ah*Bh + Ah*Bl + Al*Bh (full split). NT=2: Ah*Bh + Al*Bh (A full x B hi).
template<bool KCAP, bool RM, bool PACKC, bool BF32, int NT>
__device__ __forceinline__ void hm_body(
    const uint2* __restrict__ A, const void* __restrict__ Bv,
    void* __restrict__ Cv, const float* __restrict__ Cadd,
    int M, int K, int lda2, int ldbN, int ldc, int m0, int n0,
    const int* __restrict__ rowmap)
{
    extern __shared__ char smem[];
    const uint32_t sbase = smem_u32(smem);

    const int tid = threadIdx.x;
    const int wid = tid >> 5, lid = tid & 31;
    const int wm = (wid & 3) << 5;
    const int wn = (wid >> 2) << 5;
    const int lr = lid >> 2;
    const int ca = lid & 3;
    const int lc = ca << 1;

    const float* Bf = reinterpret_cast<const float*>(Bv);
    const uint2* Bp = reinterpret_cast<const uint2*>(Bv);
    const int b_kr2 = tid >> 4;
    const int b_n4  = (tid & 15) << 2;
    float4 vb0, vb1;

    float acc[2][4][4];
#pragma unroll
    for (int i = 0; i < 2; i++)
#pragma unroll
        for (int j = 0; j < 4; j++)
#pragma unroll
            for (int q = 0; q < 4; q++) acc[i][j][q] = 0.f;

    int Keff = K;
    if (KCAP) Keff = min(K, m0 + BM);
    const int nch = Keff >> 5;

    issue_A(sbase, A, M, lda2, m0, 0, tid);
    if (!BF32) issue_B(sbase + SMEM_A_BYTES, Bp, ldbN, n0, 0, tid);
    asm volatile("cp.async.commit_group;" ::: "memory");
    if (BF32) {
        const float* bp = Bf + (ll)(2*b_kr2)*ldbN + n0 + b_n4;
        vb0 = *reinterpret_cast<const float4*>(bp);
        vb1 = *reinterpret_cast<const float4*>(bp + ldbN);
    }

    for (int c = 0; c < nch; c++) {
        const int cur = c & 1;
        if (BF32) {
            uint2* Bsw = reinterpret_cast<uint2*>(smem + cur*SMEM_BUF + SMEM_A_BYTES);
            if (NT == 3) {
                Bsw[b_kr2*LDB2 + b_n4 + 0] = hsplit2(vb0.x, vb1.x);
                Bsw[b_kr2*LDB2 + b_n4 + 1] = hsplit2(vb0.y, vb1.y);
                Bsw[b_kr2*LDB2 + b_n4 + 2] = hsplit2(vb0.z, vb1.z);
                Bsw[b_kr2*LDB2 + b_n4 + 3] = hsplit2(vb0.w, vb1.w);
            } else {
                Bsw[b_kr2*LDB2 + b_n4 + 0] = make_uint2(hpack2(vb0.x, vb1.x), 0u);
                Bsw[b_kr2*LDB2 + b_n4 + 1] = make_uint2(hpack2(vb0.y, vb1.y), 0u);
                Bsw[b_kr2*LDB2 + b_n4 + 2] = make_uint2(hpack2(vb0.z, vb1.z), 0u);
                Bsw[b_kr2*LDB2 + b_n4 + 3] = make_uint2(hpack2(vb0.w, vb1.w), 0u);
            }
        }
        if (c + 1 < nch) {
            uint32_t nb = sbase + (uint32_t)(cur ^ 1)*SMEM_BUF;
            issue_A(nb, A, M, lda2, m0, (c + 1) << 4, tid);
            if (!BF32) issue_B(nb + SMEM_A_BYTES, Bp, ldbN, n0, (c + 1) << 4, tid);
            asm volatile("cp.async.commit_group;" ::: "memory");
            if (BF32) {
                const float* bp = Bf + (ll)(((c + 1) << 5) + 2*b_kr2)*ldbN + n0 + b_n4;
                vb0 = *reinterpret_cast<const float4*>(bp);
                vb1 = *reinterpret_cast<const float4*>(bp + ldbN);
            }
            asm volatile("cp.async.wait_group 1;" ::: "memory");
        } else {
            asm volatile("cp.async.wait_group 0;" ::: "memory");
        }
        __syncthreads();

        const uint2* As = reinterpret_cast<const uint2*>(smem + cur*SMEM_BUF);
        const uint2* Bs = reinterpret_cast<const uint2*>(smem + cur*SMEM_BUF + SMEM_A_BYTES);

#pragma unroll
        for (int s = 0; s < 2; s++) {
            const int jb = s << 3;
            uint2 bfr[4][2];
#pragma unroll
            for (int nt = 0; nt < 4; nt++) {
                int n = wn + nt*8 + lr;
                bfr[nt][0] = Bs[(jb + ca    )*LDB2 + n];
                bfr[nt][1] = Bs[(jb + ca + 4)*LDB2 + n];
            }
#pragma unroll
            for (int mt = 0; mt < 2; mt++) {
                int r = wm + mt*16 + lr;
                uint2 a0 = As[ r     *LDA2 + jb + ca    ];
                uint2 a1 = As[(r + 8)*LDA2 + jb + ca    ];
                uint2 a2 = As[ r     *LDA2 + jb + ca + 4];
                uint2 a3 = As[(r + 8)*LDA2 + jb + ca + 4];
#pragma unroll
                for (int nt = 0; nt < 4; nt++) {
                    mma_f16(acc[mt][nt], a0.x, a1.x, a2.x, a3.x, bfr[nt][0].x, bfr[nt][1].x);
                    if (NT == 3)
                        mma_f16(acc[mt][nt], a0.x, a1.x, a2.x, a3.x, bfr[nt][0].y, bfr[nt][1].y);
                    mma_f16(acc[mt][nt], a0.y, a1.y, a2.y, a3.y, bfr[nt][0].x, bfr[nt][1].x);
                }
            }
        }
        __syncthreads();
    }

#pragma unroll
    for (int mt = 0; mt < 2; mt++) {
        int mbase = m0 + wm + mt*16 + lr;
#pragma unroll
        for (int half = 0; half < 2; half++) {
            int m = mbase + half*8;
            if (m < M) {
                int srow = RM ? rowmap[m] : m;
#pragma unroll
                for (int nt = 0; nt < 4; nt++) {
                    int n = n0 + wn + nt*8 + lc;
                    float2 v = half ? make_float2(acc[mt][nt][2], acc[mt][nt][3])
                                    : make_float2(acc[mt][nt][0], acc[mt][nt][1]);
                    if (PACKC) {
                        uint2* C2 = reinterpret_cast<uint2*>(Cv);
                        C2[(ll)srow*(ldc >> 1) + (n >> 1)] = hsplit2(v.x, v.y);
                    } else {
                        float* C = reinterpret_cast<float*>(Cv);
                        if (Cadd) {
                            float2 a = *reinterpret_cast<const float2*>(Cadd + (ll)m*ldc + n);
                            v.x += a.x; v.y += a.y;
                        }
                        *reinterpret_cast<float2*>(C + (ll)srow*ldc + n) = v;
                    }
                }
            }
        }
    }
}

// ----------------------------- GEMM wrappers -------------------------------
__global__ void __launch_bounds__(256, 3) hm_dense(
    const uint2* __restrict__ A, const uint2* __restrict__ B,
    float* __restrict__ C, const float* __restrict__ Cadd,
    int M, int K, int lda2, int ldbN, int ldc)
{
    hm_body<false, false, false, false, 3>(A, B, C, Cadd, M, K, lda2, ldbN, ldc,
                                           blockIdx.x << 7, blockIdx.y << 6, nullptr);
}

// 2-term dense (sdw)
__global__ void __launch_bounds__(256, 3) hm_dense_2t(
    const uint2* __restrict__ A, const uint2* __restrict__ B,
    float* __restrict__ C, const float* __restrict__ Cadd,
    int M, int K, int lda2, int ldbN, int ldc)
{
    hm_body<false, false, false, false, 2>(A, B, C, Cadd, M, K, lda2, ldbN, ldc,
                                           blockIdx.x << 7, blockIdx.y << 6, nullptr);
}

__global__ void __launch_bounds__(256, 3) hm_dense2(
    const uint2* __restrict__ A,
    const uint2* __restrict__ B0, float* __restrict__ C0,
    const uint2* __restrict__ B1, float* __restrict__ C1,
    int M, int K, int lda2, int ldbN, int ldc)
{
    const uint2* B = blockIdx.z ? B1 : B0;
    float* C = blockIdx.z ? C1 : C0;
    hm_body<false, false, false, false, 3>(A, B, C, nullptr, M, K, lda2, ldbN, ldc,
                                           blockIdx.x << 7, blockIdx.y << 6, nullptr);
}

// 2-term paired dense (shared-expert sg/su)
__global__ void __launch_bounds__(256, 3) hm_dense2_2t(
    const uint2* __restrict__ A,
    const uint2* __restrict__ B0, float* __restrict__ C0,
    const uint2* __restrict__ B1, float* __restrict__ C1,
    int M, int K, int lda2, int ldbN, int ldc)
{
    const uint2* B = blockIdx.z ? B1 : B0;
    float* C = blockIdx.z ? C1 : C0;
    hm_body<false, false, false, false, 2>(A, B, C, nullptr, M, K, lda2, ldbN, ldc,
                                           blockIdx.x << 7, blockIdx.y << 6, nullptr);
}

__global__ void __launch_bounds__(256, 3) hm_qk(
    const uint2* __restrict__ q2, const uint2* __restrict__ kT2, float* __restrict__ scv)
{
    int h = blockIdx.z;
    int m0 = blockIdx.x << 7, n0 = blockIdx.y << 6;
    if (n0 > m0 + (BM - 1)) return;
    hm_body<false, false, false, false, 3>(q2 + h*64, kT2 + (ll)(h >> 2)*64*SQ,
                                           scv + (ll)h*SQ*SQ, nullptr,
                                           SQ, HDIM, 1024, SQ, SQ, m0, n0, nullptr);
}

__global__ void __launch_bounds__(256, 3) hm_pv(
    const uint2* __restrict__ P2, const uint2* __restrict__ v2, uint2* __restrict__ attn2)
{
    int h = blockIdx.z;
    hm_body<true, false, true, false, 3>(P2 + (ll)h*SQ*1024, v2 + (h >> 2)*HDIM,
                                         attn2 + h*(HDIM/2), nullptr,
                                         SQ, SQ, 1024, KVD, DIM, blockIdx.x << 7, blockIdx.y << 6, nullptr);
}

__global__ void __launch_bounds__(256, 2) hm_gateup(
    const uint2* __restrict__ tg2, const float* __restrict__ gup, float* __restrict__ gu)
{
    int e = blockIdx.z;
    int cnt = g_seg_count[e];
    int m0 = blockIdx.x << 7;
    if (m0 >= cnt) return;
    int st = g_seg_start[e];
    hm_body<false, false, false, true, 2>(tg2 + (ll)st*1024, gup + (ll)e*DIM*2*FDIM,
                                          gu + (ll)st*2*FDIM, nullptr,
                                          cnt, DIM, 1024, 2*FDIM, 2*FDIM, m0, blockIdx.y << 6, nullptr);
}

__global__ void __launch_bounds__(256, 2) hm_down(
    const uint2* __restrict__ act2, const float* __restrict__ dwn, float* __restrict__ outr)
{
    int e = blockIdx.z;
    int cnt = g_seg_count[e];
    int m0 = blockIdx.x << 7;
    if (m0 >= cnt) return;
    int st = g_seg_start[e];
    hm_body<false, true, false, true, 2>(act2 + (ll)st*1024, dwn + (ll)e*FDIM*DIM,
                                         outr, nullptr,
                                         cnt, FDIM, 1024, DIM, DIM, m0, blockIdx.y << 6, g_perm + st);
}

// ----------------------------- packers / converters -------------------------
__global__ void __launch_bounds__(256) conv_pb4(
    const float* __restrict__ src, uint2* __restrict__ dst, int nlog)
{
    ll i = ((ll)blockIdx.x*256 + threadIdx.x) << 2;
    ll n = i & ((1 << nlog) - 1);
    ll j = i >> nlog;
    const float4 x = *reinterpret_cast<const float4*>(src + ((j << 1)      << nlog) + n);
    const float4 y = *reinterpret_cast<const float4*>(src + (((j << 1)|1)  << nlog) + n);
    uint2 d0 = hsplit2(x.x, y.x);
    uint2 d1 = hsplit2(x.y, y.y);
    uint2 d2 = hsplit2(x.z, y.z);
    uint2 d3 = hsplit2(x.w, y.w);
    uint4* o = reinterpret_cast<uint4*>(dst + i);
    o[0] = make_uint4(d0.x, d0.y, d1.x, d1.y);
    o[1] = make_uint4(d2.x, d2.y, d3.x, d3.y);
}

__global__ void __launch_bounds__(256) rms_pack(
    const float* __restrict__ x, const float* __restrict__ w,
    float* __restrict__ y, uint2* __restrict__ y2)
{
    int row = blockIdx.x, tid = threadIdx.x;
    const float* xr = x + (ll)row*DIM;
    float s = 0.f;
    for (int d = tid; d < DIM; d += 256) { float v = xr[d]; s = fmaf(v, v, s); }
    __shared__ float red[256];
    red[tid] = s; __syncthreads();
    for (int o = 128; o > 0; o >>= 1) { if (tid < o) red[tid] += red[tid+o]; __syncthreads(); }
    float inv = rsqrtf(red[0] * (1.0f/DIM) + 1e-5f);
    for (int d2 = tid; d2 < 1024; d2 += 256) {
        float2 v = *reinterpret_cast<const float2*>(xr + 2*d2);
        float a = v.x * inv * w[2*d2];
        float b = v.y * inv * w[2*d2+1];
        if (y) *reinterpret_cast<float2*>(y + (ll)row*DIM + 2*d2) = make_float2(a, b);
        y2[(ll)row*1024 + d2] = hsplit2(a, b);
    }
}

template<int KM>
__global__ void rope_pack(const float* __restrict__ in, const float* __restrict__ cosb,
                          const float* __restrict__ sinb, uint2* __restrict__ out, int ld)
{
    int s = blockIdx.x, h = blockIdx.y, j = threadIdx.x;  // j: 0..63
    const float* p = in + (ll)s*ld + h*HDIM;
    float a = p[2*j], b = p[2*j+1];
    float c  = cosb[s*64 + j];
    float sn = sinb[s*64 + j];
    float na = a*c - b*sn;
    float nb = a*sn + b*c;
    __shared__ float red[64];
    red[j] = na*na + nb*nb; __syncthreads();
    for (int o = 32; o > 0; o >>= 1) { if (j < o) red[j] += red[j+o]; __syncthreads(); }
    float scale = rsqrtf(red[0] * (1.0f/HDIM) + 1e-6f);
    na *= scale; nb *= scale;
    if (KM == 0)
        out[(ll)s*1024 + h*64 + j] = hsplit2(na, nb);
    else
        out[(ll)(h*64 + j)*SQ + s] = hsplit2(na, nb);
}

// causal softmax -> packed PA P2; single global read pass (rows cached in regs)
__global__ void __launch_bounds__(256) softmax_pack(
    const float* __restrict__ scores, uint2* __restrict__ P2)
{
    int row = blockIdx.x, h = blockIdx.y, tid = threadIdx.x;
    const float* p = scores + ((ll)h*SQ + row)*SQ;
    uint2* o = P2 + ((ll)h*SQ + row)*1024;
    int n = row + 1;
    int np = (n + 1) >> 1;
    int zend2 = ((row >> 7) << 6) + 64;
    __shared__ float red[256];

    float2 xv[4];
    float mx = -1e30f;
#pragma unroll
    for (int k = 0; k < 4; k++) {
        int j2 = tid + (k << 8);
        float2 v = make_float2(-1e30f, -1e30f);
        if (j2 < np) {
            v = *reinterpret_cast<const float2*>(p + 2*j2);
            v.x *= kScaling;
            v.y = (2*j2 + 1 < n) ? v.y * kScaling : -1e30f;
        }
        xv[k] = v;
        mx = fmaxf(mx, fmaxf(v.x, v.y));
    }
    red[tid] = mx; __syncthreads();
    for (int q = 128; q > 0; q >>= 1) { if (tid < q) red[tid] = fmaxf(red[tid], red[tid+q]); __syncthreads(); }
    mx = red[0]; __syncthreads();

    float sum = 0.f;
#pragma unroll
    for (int k = 0; k < 4; k++) {
        int j2 = tid + (k << 8);
        float e0 = expf(xv[k].x - mx);
        float e1 = expf(xv[k].y - mx);
        xv[k] = make_float2(e0, e1);
        if (j2 < np) sum += e0 + e1;
    }
    red[tid] = sum; __syncthreads();
    for (int q = 128; q > 0; q >>= 1) { if (tid < q) red[tid] += red[tid+q]; __syncthreads(); }
    float inv = 1.f / red[0];

#pragma unroll
    for (int k = 0; k < 4; k++) {
        int j2 = tid + (k << 8);
        if (j2 < np) o[j2] = hsplit2(xv[k].x*inv, xv[k].y*inv);
    }
    for (int j2 = np + tid; j2 < zend2; j2 += 256) o[j2] = make_uint2(0u, 0u);
}

__global__ void __launch_bounds__(256) router_kernel(
    const float* __restrict__ t, const float* __restrict__ rw)
{
    int row = blockIdx.x, tid = threadIdx.x;
    float acc[NEXP] = {};
    const float* xr = t + (ll)row*DIM;
    for (int d = tid; d < DIM; d += 256) {
        float x = xr[d];
        const float* r = rw + d*NEXP;
#pragma unroll
        for (int e = 0; e < NEXP; e++) acc[e] = fmaf(x, r[e], acc[e]);
    }
    __shared__ float red[NEXP][256];
#pragma unroll
    for (int e = 0; e < NEXP; e++) red[e][tid] = acc[e];
    __syncthreads();
    for (int o = 128; o > 0; o >>= 1) {
        if (tid < o)
#pragma unroll
            for (int e = 0; e < NEXP; e++) red[e][tid] += red[e][tid+o];
        __syncthreads();
    }
    if (tid == 0) {
        float best = red[0][0]; int bi = 0;
#pragma unroll
        for (int e = 1; e < NEXP; e++) if (red[e][0] > best) { best = red[e][0]; bi = e; }
        g_eidx[row] = bi;
        g_gateval[row] = 1.f / (1.f + expf(-best));
        atomicAdd(&g_hist[bi], 1);
    }
}

__global__ void zero8_kernel() {
    int i = threadIdx.x;
    if (i < NEXP) { g_hist[i] = 0; g_ctr[i] = 0; }
}
__global__ void prefix_kernel() {
    if (threadIdx.x == 0) {
        int s = 0;
        for (int e = 0; e < NEXP; e++) { g_seg_start[e] = s; g_seg_count[e] = g_hist[e]; s += g_hist[e]; }
        g_seg_start[NEXP] = s;
    }
}
__global__ void scatter_kernel() {
    int tk = blockIdx.x*256 + threadIdx.x;
    if (tk < NTOK) {
        int e = g_eidx[tk];
        int pos = atomicAdd(&g_ctr[e], 1);
        g_perm[g_seg_start[e] + pos] = tk;
    }
}

__global__ void __launch_bounds__(256) gather_pack(const float* __restrict__ t) {
    int i = blockIdx.x;
    int s = g_perm[i];
    float g = g_gateval[s];
    const float* src = t + (ll)s*DIM;
    for (int d2 = threadIdx.x; d2 < 1024; d2 += 256) {
        float2 v = *reinterpret_cast<const float2*>(src + 2*d2);
        g2_tg[(ll)i*1024 + d2] = hsplit2(v.x*g, v.y*g);
    }
}

__global__ void __launch_bounds__(256) act_pack(const float* __restrict__ gu) {
    ll i2 = (ll)blockIdx.x*256 + threadIdx.x;
    ll row = i2 >> 10, f2 = i2 & 1023;
    const float* r = gu + row*2*FDIM;
    float g0 = r[2*f2], g1 = r[2*f2+1];
    float u0 = r[FDIM + 2*f2], u1 = r[FDIM + 2*f2+1];
    float a0 = u0 * (g0 / (1.f + expf(-g0)));
    float a1 = u1 * (g1 / (1.f + expf(-g1)));
    g2_act[i2] = hsplit2(a0, a1);
}

__global__ void __launch_bounds__(256) swiglu_pack(
    const float* __restrict__ g, const float* __restrict__ u)
{
    ll i2 = (ll)blockIdx.x*256 + threadIdx.x;
    float g0 = g[2*i2], g1 = g[2*i2+1];
    float u0 = u[2*i2], u1 = u[2*i2+1];
    float a0 = u0 * (g0 / (1.f + expf(-g0)));
    float a1 = u1 * (g1 / (1.f + expf(-g1)));
    g2_sg[i2] = hsplit2(a0, a1);
}

__global__ void __launch_bounds__(256) final_add_kernel(
    const float* __restrict__ hs2, const float* __restrict__ shared_,
    const float* __restrict__ routed, float* __restrict__ out)
{
    ll i = (ll)blockIdx.x*256 + threadIdx.x;
    out[i] = hs2[i] + shared_[i] + routed[i];
}

// ----------------------------- launcher ------------------------------------
static void* symp(const void* sym) { void* p = nullptr; cudaGetSymbolAddress(&p, sym); return p; }

extern "C" void kernel_launch(void* const* d_in, const int* in_sizes, int n_in,
                              void* d_out, int out_size)
{
    (void)in_sizes; (void)n_in; (void)out_size;
    const float* hidden = (const float*)d_in[0];
    const float* fcos   = (const float*)d_in[1];
    const float* fsin   = (const float*)d_in[2];
    const float* wq     = (const float*)d_in[5];
    const float* wk     = (const float*)d_in[6];
    const float* wv     = (const float*)d_in[7];
    const float* wo     = (const float*)d_in[8];
    const float* ln1    = (const float*)d_in[9];
    const float* ln2    = (const float*)d_in[10];
    const float* rw     = (const float*)d_in[11];
    const float* gup    = (const float*)d_in[12];
    const float* dwn    = (const float*)d_in[13];
    const float* sgw    = (const float*)d_in[14];
    const float* suw    = (const float*)d_in[15];
    const float* sdw    = (const float*)d_in[16];
    float* out = (float*)d_out;

    float* qb     = (float*)symp(g_q);
    float* kb     = (float*)symp(g_k);
    float* vb     = (float*)symp(g_v);
    float* sc     = (float*)symp(g_scores);
    float* hs2    = (float*)symp(g_hs2);
    float* tb     = (float*)symp(g_t);
    float* gu     = (float*)symp(g_gu);
    float* sg     = (float*)symp(g_sg);
    float* su     = (float*)symp(g_su);
    float* routed = (float*)symp(g_routed);
    float* shd    = (float*)symp(g_shared);
    uint2* hsn2   = (uint2*)symp(g2_hsn);
    uint2* q2     = (uint2*)symp(g2_q);
    uint2* kT2    = (uint2*)symp(g2_kT);
    uint2* v2     = (uint2*)symp(g2_v);
    uint2* P2     = (uint2*)symp(g2_P);
    uint2* attn2  = (uint2*)symp(g2_attn);
    uint2* tb2    = (uint2*)symp(g2_t);
    uint2* tg2    = (uint2*)symp(g2_tg);
    uint2* act2   = (uint2*)symp(g2_act);
    uint2* sg2    = (uint2*)symp(g2_sg);
    uint2* wq2    = (uint2*)symp(g2_wq);
    uint2* wk2    = (uint2*)symp(g2_wk);
    uint2* wv2    = (uint2*)symp(g2_wv);
    uint2* wo2    = (uint2*)symp(g2_wo);
    uint2* sgw2   = (uint2*)symp(g2_sgw);
    uint2* suw2   = (uint2*)symp(g2_suw);
    uint2* sdw2   = (uint2*)symp(g2_sdw);

    cudaFuncSetAttribute(hm_dense,     cudaFuncAttributeMaxDynamicSharedMemorySize, SMEM_BYTES);
    cudaFuncSetAttribute(hm_dense_2t,  cudaFuncAttributeMaxDynamicSharedMemorySize, SMEM_BYTES);
    cudaFuncSetAttribute(hm_dense2,    cudaFuncAttributeMaxDynamicSharedMemorySize, SMEM_BYTES);
    cudaFuncSetAttribute(hm_dense2_2t, cudaFuncAttributeMaxDynamicSharedMemorySize, SMEM_BYTES);
    cudaFuncSetAttribute(hm_qk,        cudaFuncAttributeMaxDynamicSharedMemorySize, SMEM_BYTES);
    cudaFuncSetAttribute(hm_pv,        cudaFuncAttributeMaxDynamicSharedMemorySize, SMEM_BYTES);
    cudaFuncSetAttribute(hm_gateup,    cudaFuncAttributeMaxDynamicSharedMemorySize, SMEM_BYTES);
    cudaFuncSetAttribute(hm_down,      cudaFuncAttributeMaxDynamicSharedMemorySize, SMEM_BYTES);

    // 0) small-weight conversions (reused 16x by dense GEMMs)
    conv_pb4<<<2048, 256>>>(wq,  wq2,  11);
    conv_pb4<<< 512, 256>>>(wk,  wk2,   9);
    conv_pb4<<< 512, 256>>>(wv,  wv2,   9);
    conv_pb4<<<2048, 256>>>(wo,  wo2,  11);
    conv_pb4<<<2048, 256>>>(sgw, sgw2, 11);
    conv_pb4<<<2048, 256>>>(suw, suw2, 11);
    conv_pb4<<<2048, 256>>>(sdw, sdw2, 11);

    // 1) pre-attn RMSNorm (packed only)
    rms_pack<<<NTOK, 256>>>(hidden, ln1, nullptr, hsn2);
    // 2) QKV projections (3-term)
    hm_dense <<<dim3(16,32),  256, SMEM_BYTES>>>(hsn2, wq2, qb, nullptr, NTOK, DIM, 1024, 2048, 2048);
    hm_dense2<<<dim3(16,8,2), 256, SMEM_BYTES>>>(hsn2, wk2, kb, wv2, vb, NTOK, DIM, 1024, 512, 512);
    // 3) RoPE + L2 norm -> packed q2 / transposed kT2; pack v2
    rope_pack<0><<<dim3(SQ, NHEADS), 64>>>(qb, fcos, fsin, q2, DIM);
    rope_pack<1><<<dim3(SQ, NKV),    64>>>(kb, fcos, fsin, kT2, KVD);
    conv_pb4<<<512, 256>>>(vb, v2, 9);
    // 4) scores = Q K^T (3-term, causal tile skip)
    hm_qk<<<dim3(16,32,NHEADS), 256, SMEM_BYTES>>>(q2, kT2, sc);
    // 5) causal softmax -> packed P2 (single-pass)
    softmax_pack<<<dim3(SQ, NHEADS), 256>>>(sc, P2);
    // 6) attn = P V (3-term, K capped), packed epilogue
    hm_pv<<<dim3(16,2,NHEADS), 256, SMEM_BYTES>>>(P2, v2, attn2);
    // 7) output proj + residual (3-term)
    hm_dense<<<dim3(16,32), 256, SMEM_BYTES>>>(attn2, wo2, hs2, hidden, NTOK, DIM, 1024, 2048, 2048);
    // 8) post-attn RMSNorm (fp32 + packed)
    rms_pack<<<NTOK, 256>>>(hs2, ln2, tb, tb2);
    // 9) router
    zero8_kernel<<<1, 32>>>();
    router_kernel<<<NTOK, 256>>>(tb, rw);
    prefix_kernel<<<1, 32>>>();
    scatter_kernel<<<8, 256>>>();
    gather_pack<<<NTOK, 256>>>(tb);
    // 10) routed expert (2-term, B fp32 hi-only split in-kernel)
    hm_gateup<<<dim3(16,64,NEXP), 256, SMEM_BYTES>>>(tg2, gup, gu);
    act_pack<<<(NTOK*1024)/256, 256>>>(gu);
    hm_down<<<dim3(16,32,NEXP), 256, SMEM_BYTES>>>(act2, dwn, routed);
    // 11) shared expert (2-term)
    hm_dense2_2t<<<dim3(16,32,2), 256, SMEM_BYTES>>>(tb2, sgw2, sg, suw2, su, NTOK, DIM, 1024, 2048, 2048);
    swiglu_pack<<<(NTOK*1024)/256, 256>>>(sg, su);
    hm_dense_2t<<<dim3(16,32), 256, SMEM_BYTES>>>(sg2, sdw2, shd, nullptr, NTOK, FDIM, 1024, 2048, 2048);
    // 12) final residual + shared + routed
    final_add_kernel<<<(NTOK*DIM)/256, 256>>>(hs2, shd, routed, out);
}

// round 15
// speedup vs baseline: 2.0134x; 1.0666x over previous
#include <cuda_runtime.h>
#include <cuda_bf16.h>
#include <cstdint>
#include <math.h>

typedef long long ll;

#define SQ     2048
#define DIM    2048
#define NHEADS 16
#define NKV    4
#define HDIM   128
#define KVD    512
#define NEXP   8
#define FDIM   2048
#define NTOK   2048

#define BM 128
#define BN 64
#define BK 32
#define LDA2 20
#define LDB2 68
#define SMEM_A_BYTES (BM*LDA2*8)              // 20480
#define SMEM_B_BYTES ((BK/2)*LDB2*8)          // 8704
#define SMEM_BUF     (SMEM_A_BYTES + SMEM_B_BYTES)   // 29184
#define SMEM_BYTES   (2*SMEM_BUF)             // 58368

static const float kScaling = 0.08838834764831845f;  // 128^-0.5

// ----------------------------- scratch (device globals) --------------------
__device__ float g_q     [(ll)NTOK*DIM];
__device__ float g_k     [(ll)NTOK*KVD];
__device__ float g_v     [(ll)NTOK*KVD];
__device__ float g_scores[(ll)NHEADS*SQ*SQ];
__device__ float g_hs2   [(ll)NTOK*DIM];
__device__ float g_t     [(ll)NTOK*DIM];
__device__ float g_gu    [(ll)NTOK*2*FDIM];
__device__ float g_sg    [(ll)NTOK*FDIM];
__device__ float g_su    [(ll)NTOK*FDIM];
__device__ float g_routed[(ll)NTOK*DIM];
__device__ float g_shared[(ll)NTOK*DIM];
// packed split-fp16 (uint2 = {hi_pair, lo_pair} along k)
__device__ uint2 g2_hsn [(ll)NTOK*1024];
__device__ uint2 g2_q   [(ll)NTOK*1024];
__device__ uint2 g2_kT  [(ll)NKV*64*SQ];
__device__ uint2 g2_v   [(ll)1024*KVD];
__device__ uint2 g2_P   [(ll)NHEADS*SQ*1024];
__device__ uint2 g2_attn[(ll)NTOK*1024];
__device__ uint2 g2_t   [(ll)NTOK*1024];
__device__ uint2 g2_tg  [(ll)NTOK*1024];
__device__ uint2 g2_act [(ll)NTOK*1024];
__device__ uint2 g2_sg  [(ll)NTOK*1024];
__device__ uint2 g2_wq  [(ll)1024*2048];
__device__ uint2 g2_wk  [(ll)1024*512];
__device__ uint2 g2_wv  [(ll)1024*512];
__device__ uint2 g2_wo  [(ll)1024*2048];
__device__ uint2 g2_sgw [(ll)1024*2048];
__device__ uint2 g2_suw [(ll)1024*2048];
__device__ uint2 g2_sdw [(ll)1024*2048];
// router state
__device__ int   g_eidx[NTOK];
__device__ float g_gateval[NTOK];
__device__ int   g_hist[NEXP], g_ctr[NEXP], g_seg_start[NEXP+1], g_seg_count[NEXP];
__device__ int   g_perm[NTOK];

// ----------------------------- helpers -------------------------------------
__device__ __forceinline__ uint32_t smem_u32(const void* p) {
    uint32_t a;
    asm("{ .reg .u64 t; cvta.to.shared.u64 t, %1; cvt.u32.u64 %0, t; }" : "=r"(a) : "l"(p));
    return a;
}
// split (x,y) -> {hi_pair, lo_pair}
__device__ __forceinline__ uint2 hsplit2(float x, float y) {
    uint2 r;
    asm("{\n\t"
        ".reg .b16 hx,hy;\n\t"
        ".reg .f32 fx,fy,rx,ry;\n\t"
        "cvt.rn.f16x2.f32 %0, %3, %2;\n\t"
        "mov.b32 {hx,hy}, %0;\n\t"
        "cvt.f32.f16 fx, hx;\n\t"
        "cvt.f32.f16 fy, hy;\n\t"
        "sub.f32 rx, %2, fx;\n\t"
        "sub.f32 ry, %3, fy;\n\t"
        "cvt.rn.f16x2.f32 %1, ry, rx;\n\t"
        "}" : "=r"(r.x), "=r"(r.y) : "f"(x), "f"(y));
    return r;
}
// hi-only pack (for 2-term B): one packed convert
__device__ __forceinline__ uint32_t hpack2(float x, float y) {
    uint32_t r;
    asm("cvt.rn.f16x2.f32 %0, %2, %1;" : "=r"(r) : "f"(x), "f"(y));
    return r;
}
__device__ __forceinline__ void mma_f16(float* c, uint32_t a0, uint32_t a1, uint32_t a2, uint32_t a3,
                                        uint32_t b0, uint32_t b1) {
    asm volatile("mma.sync.aligned.m16n8k16.row.col.f32.f16.f16.f32 "
        "{%0,%1,%2,%3}, {%4,%5,%6,%7}, {%8,%9}, {%0,%1,%2,%3};"
        : "+f"(c[0]), "+f"(c[1]), "+f"(c[2]), "+f"(c[3])
        : "r"(a0), "r"(a1), "r"(a2), "r"(a3), "r"(b0), "r"(b1));
}
__device__ __forceinline__ void cpa16(uint32_t dst, const void* src, int szbytes) {
    asm volatile("cp.async.cg.shared.global [%0], [%1], 16, %2;"
        :: "r"(dst), "l"(src), "r"(szbytes));
}

// ----------------------------- GEMM tile copy helpers -----------------------
__device__ __forceinline__ void issue_A(
    uint32_t sa, const uint2* __restrict__ A,
    int M, int lda2, int m0, int jbase, int tid)
{
#pragma unroll
    for (int i = 0; i < 4; i++) {
        int chunk = tid + (i << 8);
        int row = chunk >> 3, sp = (chunk & 7) << 1;
        int gm = m0 + row;
        int ok = (gm < M) ? 16 : 0;
        const uint2* src = A + (ll)min(gm, M - 1)*lda2 + jbase + sp;
        cpa16(sa + (uint32_t)(row*LDA2 + sp)*8u, src, ok);
    }
}
__device__ __forceinline__ void issue_B(
    uint32_t sb, const uint2* __restrict__ B,
    int ldbN, int n0, int jbase, int tid)
{
#pragma unroll
    for (int i = 0; i < 2; i++) {
        int chunk = tid + (i << 8);
        int jr = chunk >> 5, nq = (chunk & 31) << 1;
        const uint2* src = B + (ll)(jbase + jr)*ldbN + n0 + nq;
        cpa16(sb + (uint32_t)(jr*LDB2 + nq)*8u, src, 16);
    }
}

// ----------------------------- tensor GEMM body -----------------------------
// NT=3: Ah*Bh + Ah*Bl + Al*Bh (full split). NT=2: Ah*Bh + Al*Bh (A full x B hi).
template<bool KCAP, bool RM, bool PACKC, bool BF32, int NT>
__device__ __forceinline__ void hm_body(
    const uint2* __restrict__ A, const void* __restrict__ Bv,
    void* __restrict__ Cv, const float* __restrict__ Cadd,
    int M, int K, int lda2, int ldbN, int ldc, int m0, int n0,
    const int* __restrict__ rowmap)
{
    extern __shared__ char smem[];
    const uint32_t sbase = smem_u32(smem);

    const int tid = threadIdx.x;
    const int wid = tid >> 5, lid = tid & 31;
    const int wm = (wid & 3) << 5;
    const int wn = (wid >> 2) << 5;
    const int lr = lid >> 2;
    const int ca = lid & 3;
    const int lc = ca << 1;

    const float* Bf = reinterpret_cast<const float*>(Bv);
    const uint2* Bp = reinterpret_cast<const uint2*>(Bv);
    const int b_kr2 = tid >> 4;
    const int b_n4  = (tid & 15) << 2;
    float4 vb0, vb1;

    float acc[2][4][4];
#pragma unroll
    for (int i = 0; i < 2; i++)
#pragma unroll
        for (int j = 0; j < 4; j++)
#pragma unroll
            for (int q = 0; q < 4; q++) acc[i][j][q] = 0.f;

    int Keff = K;
    if (KCAP) Keff = min(K, m0 + BM);
    const int nch = Keff >> 5;

    issue_A(sbase, A, M, lda2, m0, 0, tid);
    if (!BF32) issue_B(sbase + SMEM_A_BYTES, Bp, ldbN, n0, 0, tid);
    asm volatile("cp.async.commit_group;" ::: "memory");
    if (BF32) {
        const float* bp = Bf + (ll)(2*b_kr2)*ldbN + n0 + b_n4;
        vb0 = *reinterpret_cast<const float4*>(bp);
        vb1 = *reinterpret_cast<const float4*>(bp + ldbN);
    }

    for (int c = 0; c < nch; c++) {
        const int cur = c & 1;
        if (BF32) {
            uint2* Bsw = reinterpret_cast<uint2*>(smem + cur*SMEM_BUF + SMEM_A_BYTES);
            if (NT == 3) {
                Bsw[b_kr2*LDB2 + b_n4 + 0] = hsplit2(vb0.x, vb1.x);
                Bsw[b_kr2*LDB2 + b_n4 + 1] = hsplit2(vb0.y, vb1.y);
                Bsw[b_kr2*LDB2 + b_n4 + 2] = hsplit2(vb0.z, vb1.z);
                Bsw[b_kr2*LDB2 + b_n4 + 3] = hsplit2(vb0.w, vb1.w);
            } else {
                Bsw[b_kr2*LDB2 + b_n4 + 0] = make_uint2(hpack2(vb0.x, vb1.x), 0u);
                Bsw[b_kr2*LDB2 + b_n4 + 1] = make_uint2(hpack2(vb0.y, vb1.y), 0u);
                Bsw[b_kr2*LDB2 + b_n4 + 2] = make_uint2(hpack2(vb0.z, vb1.z), 0u);
                Bsw[b_kr2*LDB2 + b_n4 + 3] = make_uint2(hpack2(vb0.w, vb1.w), 0u);
            }
        }
        if (c + 1 < nch) {
            uint32_t nb = sbase + (uint32_t)(cur ^ 1)*SMEM_BUF;
            issue_A(nb, A, M, lda2, m0, (c + 1) << 4, tid);
            if (!BF32) issue_B(nb + SMEM_A_BYTES, Bp, ldbN, n0, (c + 1) << 4, tid);
            asm volatile("cp.async.commit_group;" ::: "memory");
            if (BF32) {
                const float* bp = Bf + (ll)(((c + 1) << 5) + 2*b_kr2)*ldbN + n0 + b_n4;
                vb0 = *reinterpret_cast<const float4*>(bp);
                vb1 = *reinterpret_cast<const float4*>(bp + ldbN);
            }
            asm volatile("cp.async.wait_group 1;" ::: "memory");
        } else {
            asm volatile("cp.async.wait_group 0;" ::: "memory");
        }
        __syncthreads();

        const uint2* As = reinterpret_cast<const uint2*>(smem + cur*SMEM_BUF);
        const uint2* Bs = reinterpret_cast<const uint2*>(smem + cur*SMEM_BUF + SMEM_A_BYTES);

#pragma unroll
        for (int s = 0; s < 2; s++) {
            const int jb = s << 3;
            uint2 bfr[4][2];
#pragma unroll
            for (int nt = 0; nt < 4; nt++) {
                int n = wn + nt*8 + lr;
                bfr[nt][0] = Bs[(jb + ca    )*LDB2 + n];
                bfr[nt][1] = Bs[(jb + ca + 4)*LDB2 + n];
            }
#pragma unroll
            for (int mt = 0; mt < 2; mt++) {
                int r = wm + mt*16 + lr;
                uint2 a0 = As[ r     *LDA2 + jb + ca    ];
                uint2 a1 = As[(r + 8)*LDA2 + jb + ca    ];
                uint2 a2 = As[ r     *LDA2 + jb + ca + 4];
                uint2 a3 = As[(r + 8)*LDA2 + jb + ca + 4];
#pragma unroll
                for (int nt = 0; nt < 4; nt++) {
                    mma_f16(acc[mt][nt], a0.x, a1.x, a2.x, a3.x, bfr[nt][0].x, bfr[nt][1].x);
                    if (NT == 3)
                        mma_f16(acc[mt][nt], a0.x, a1.x, a2.x, a3.x, bfr[nt][0].y, bfr[nt][1].y);
                    mma_f16(acc[mt][nt], a0.y, a1.y, a2.y, a3.y, bfr[nt][0].x, bfr[nt][1].x);
                }
            }
        }
        __syncthreads();
    }

#pragma unroll
    for (int mt = 0; mt < 2; mt++) {
        int mbase = m0 + wm + mt*16 + lr;
#pragma unroll
        for (int half = 0; half < 2; half++) {
            int m = mbase + half*8;
            if (m < M) {
                int srow = RM ? rowmap[m] : m;
#pragma unroll
                for (int nt = 0; nt < 4; nt++) {
                    int n = n0 + wn + nt*8 + lc;
                    float2 v = half ? make_float2(acc[mt][nt][2], acc[mt][nt][3])
                                    : make_float2(acc[mt][nt][0], acc[mt][nt][1]);
                    if (PACKC) {
                        uint2* C2 = reinterpret_cast<uint2*>(Cv);
                        C2[(ll)srow*(ldc >> 1) + (n >> 1)] = hsplit2(v.x, v.y);
                    } else {
                        float* C = reinterpret_cast<float*>(Cv);
                        if (Cadd) {
                            float2 a = *reinterpret_cast<const float2*>(Cadd + (ll)m*ldc + n);
                            v.x += a.x; v.y += a.y;
                        }
                        *reinterpret_cast<float2*>(C + (ll)srow*ldc + n) = v;
                    }
                }
            }
        }
    }
}

// ----------------------------- GEMM wrappers -------------------------------
__global__ void __launch_bounds__(256, 3) hm_dense(
    const uint2* __restrict__ A, const uint2* __restrict__ B,
    float* __restrict__ C, const float* __restrict__ Cadd,
    int M, int K, int lda2, int ldbN, int ldc)
{
    hm_body<false, false, false, false, 3>(A, B, C, Cadd, M, K, lda2, ldbN, ldc,
                                           blockIdx.x << 7, blockIdx.y << 6, nullptr);
}

// 2-term dense (sdw)
__global__ void __launch_bounds__(256, 3) hm_dense_2t(
    const uint2* __restrict__ A, const uint2* __restrict__ B,
    float* __restrict__ C, const float* __restrict__ Cadd,
    int M, int K, int lda2, int ldbN, int ldc)
{
    hm_body<false, false, false, false, 2>(A, B, C, Cadd, M, K, lda2, ldbN, ldc,
                                           blockIdx.x << 7, blockIdx.y << 6, nullptr);
}

__global__ void __launch_bounds__(256, 3) hm_dense2(
    const uint2* __restrict__ A,
    const uint2* __restrict__ B0, float* __restrict__ C0,
    const uint2* __restrict__ B1, float* __restrict__ C1,
    int M, int K, int lda2, int ldbN, int ldc)
{
    const uint2* B = blockIdx.z ? B1 : B0;
    float* C = blockIdx.z ? C1 : C0;
    hm_body<false, false, false, false, 3>(A, B, C, nullptr, M, K, lda2, ldbN, ldc,
                                           blockIdx.x << 7, blockIdx.y << 6, nullptr);
}

// 2-term paired dense (shared-expert sg/su)
__global__ void __launch_bounds__(256, 3) hm_dense2_2t(
    const uint2* __restrict__ A,
    const uint2* __restrict__ B0, float* __restrict__ C0,
    const uint2* __restrict__ B1, float* __restrict__ C1,
    int M, int K, int lda2, int ldbN, int ldc)
{
    const uint2* B = blockIdx.z ? B1 : B0;
    float* C = blockIdx.z ? C1 : C0;
    hm_body<false, false, false, false, 2>(A, B, C, nullptr, M, K, lda2, ldbN, ldc,
                                           blockIdx.x << 7, blockIdx.y << 6, nullptr);
}

__global__ void __launch_bounds__(256, 3) hm_qk(
    const uint2* __restrict__ q2, const uint2* __restrict__ kT2, float* __restrict__ scv)
{
    int h = blockIdx.z;
    int m0 = blockIdx.x << 7, n0 = blockIdx.y << 6;
    if (n0 > m0 + (BM - 1)) return;
    hm_body<false, false, false, false, 3>(q2 + h*64, kT2 + (ll)(h >> 2)*64*SQ,
                                           scv + (ll)h*SQ*SQ, nullptr,
                                           SQ, HDIM, 1024, SQ, SQ, m0, n0, nullptr);
}

__global__ void __launch_bounds__(256, 3) hm_pv(
    const uint2* __restrict__ P2, const uint2* __restrict__ v2, uint2* __restrict__ attn2)
{
    int h = blockIdx.z;
    hm_body<true, false, true, false, 3>(P2 + (ll)h*SQ*1024, v2 + (h >> 2)*HDIM,
                                         attn2 + h*(HDIM/2), nullptr,
                                         SQ, SQ, 1024, KVD, DIM, blockIdx.x << 7, blockIdx.y << 6, nullptr);
}

__global__ void __launch_bounds__(256, 2) hm_gateup(
    const uint2* __restrict__ tg2, const float* __restrict__ gup, float* __restrict__ gu)
{
    int e = blockIdx.z;
    int cnt = g_seg_count[e];
    int m0 = blockIdx.x << 7;
    if (m0 >= cnt) return;
    int st = g_seg_start[e];
    hm_body<false, false, false, true, 2>(tg2 + (ll)st*1024, gup + (ll)e*DIM*2*FDIM,
                                          gu + (ll)st*2*FDIM, nullptr,
                                          cnt, DIM, 1024, 2*FDIM, 2*FDIM, m0, blockIdx.y << 6, nullptr);
}

__global__ void __launch_bounds__(256, 2) hm_down(
    const uint2* __restrict__ act2, const float* __restrict__ dwn, float* __restrict__ outr)
{
    int e = blockIdx.z;
    int cnt = g_seg_count[e];
    int m0 = blockIdx.x << 7;
    if (m0 >= cnt) return;
    int st = g_seg_start[e];
    hm_body<false, true, false, true, 2>(act2 + (ll)st*1024, dwn + (ll)e*FDIM*DIM,
                                         outr, nullptr,
                                         cnt, FDIM, 1024, DIM, DIM, m0, blockIdx.y << 6, g_perm + st);
}

// ----------------------------- packers / converters -------------------------
__global__ void __launch_bounds__(256) conv_pb4(
    const float* __restrict__ src, uint2* __restrict__ dst, int nlog)
{
    ll i = ((ll)blockIdx.x*256 + threadIdx.x) << 2;
    ll n = i & ((1 << nlog) - 1);
    ll j = i >> nlog;
    const float4 x = *reinterpret_cast<const float4*>(src + ((j << 1)      << nlog) + n);
    const float4 y = *reinterpret_cast<const float4*>(src + (((j << 1)|1)  << nlog) + n);
    uint2 d0 = hsplit2(x.x, y.x);
    uint2 d1 = hsplit2(x.y, y.y);
    uint2 d2 = hsplit2(x.z, y.z);
    uint2 d3 = hsplit2(x.w, y.w);
    uint4* o = reinterpret_cast<uint4*>(dst + i);
    o[0] = make_uint4(d0.x, d0.y, d1.x, d1.y);
    o[1] = make_uint4(d2.x, d2.y, d3.x, d3.y);
}

__global__ void __launch_bounds__(256) rms_pack(
    const float* __restrict__ x, const float* __restrict__ w,
    float* __restrict__ y, uint2* __restrict__ y2)
{
    int row = blockIdx.x, tid = threadIdx.x;
    const float* xr = x + (ll)row*DIM;
    float s = 0.f;
    for (int d = tid; d < DIM; d += 256) { float v = xr[d]; s = fmaf(v, v, s); }
    __shared__ float red[256];
    red[tid] = s; __syncthreads();
    for (int o = 128; o > 0; o >>= 1) { if (tid < o) red[tid] += red[tid+o]; __syncthreads(); }
    float inv = rsqrtf(red[0] * (1.0f/DIM) + 1e-5f);
    for (int d2 = tid; d2 < 1024; d2 += 256) {
        float2 v = *reinterpret_cast<const float2*>(xr + 2*d2);
        float a = v.x * inv * w[2*d2];
        float b = v.y * inv * w[2*d2+1];
        if (y) *reinterpret_cast<float2*>(y + (ll)row*DIM + 2*d2) = make_float2(a, b);
        y2[(ll)row*1024 + d2] = hsplit2(a, b);
    }
}

template<int KM>
__global__ void rope_pack(const float* __restrict__ in, const float* __restrict__ cosb,
                          const float* __restrict__ sinb, uint2* __restrict__ out, int ld)
{
    int s = blockIdx.x, h = blockIdx.y, j = threadIdx.x;  // j: 0..63
    const float* p = in + (ll)s*ld + h*HDIM;
    float a = p[2*j], b = p[2*j+1];
    float c  = cosb[s*64 + j];
    float sn = sinb[s*64 + j];
    float na = a*c - b*sn;
    float nb = a*sn + b*c;
    __shared__ float red[64];
    red[j] = na*na + nb*nb; __syncthreads();
    for (int o = 32; o > 0; o >>= 1) { if (j < o) red[j] += red[j+o]; __syncthreads(); }
    float scale = rsqrtf(red[0] * (1.0f/HDIM) + 1e-6f);
    na *= scale; nb *= scale;
    if (KM == 0)
        out[(ll)s*1024 + h*64 + j] = hsplit2(na, nb);
    else
        out[(ll)(h*64 + j)*SQ + s] = hsplit2(na, nb);
}

// causal softmax -> packed PA P2; single global read pass (rows cached in regs)
__global__ void __launch_bounds__(256) softmax_pack(
    const float* __restrict__ scores, uint2* __restrict__ P2)
{
    int row = blockIdx.x, h = blockIdx.y, tid = threadIdx.x;
    const float* p = scores + ((ll)h*SQ + row)*SQ;
    uint2* o = P2 + ((ll)h*SQ + row)*1024;
    int n = row + 1;
    int np = (n + 1) >> 1;
    int zend2 = ((row >> 7) << 6) + 64;
    __shared__ float red[256];

    float2 xv[4];
    float mx = -1e30f;
#pragma unroll
    for (int k = 0; k < 4; k++) {
        int j2 = tid + (k << 8);
        float2 v = make_float2(-1e30f, -1e30f);
        if (j2 < np) {
            v = *reinterpret_cast<const float2*>(p + 2*j2);
            v.x *= kScaling;
            v.y = (2*j2 + 1 < n) ? v.y * kScaling : -1e30f;
        }
        xv[k] = v;
        mx = fmaxf(mx, fmaxf(v.x, v.y));
    }
    red[tid] = mx; __syncthreads();
    for (int q = 128; q > 0; q >>= 1) { if (tid < q) red[tid] = fmaxf(red[tid], red[tid+q]); __syncthreads(); }
    mx = red[0]; __syncthreads();

    float sum = 0.f;
#pragma unroll
    for (int k = 0; k < 4; k++) {
        int j2 = tid + (k << 8);
        float e0 = expf(xv[k].x - mx);
        float e1 = expf(xv[k].y - mx);
        xv[k] = make_float2(e0, e1);
        if (j2 < np) sum += e0 + e1;
    }
    red[tid] = sum; __syncthreads();
    for (int q = 128; q > 0; q >>= 1) { if (tid < q) red[tid] += red[tid+q]; __syncthreads(); }
    float inv = 1.f / red[0];

#pragma unroll
    for (int k = 0; k < 4; k++) {
        int j2 = tid + (k << 8);
        if (j2 < np) o[j2] = hsplit2(xv[k].x*inv, xv[k].y*inv);
    }
    for (int j2 = np + tid; j2 < zend2; j2 += 256) o[j2] = make_uint2(0u, 0u);
}

__global__ void __launch_bounds__(256) router_kernel(
    const float* __restrict__ t, const float* __restrict__ rw)
{
    int row = blockIdx.x, tid = threadIdx.x;
    float acc[NEXP] = {};
    const float* xr = t + (ll)row*DIM;
    for (int d = tid; d < DIM; d += 256) {
        float x = xr[d];
        const float* r = rw + d*NEXP;
#pragma unroll
        for (int e = 0; e < NEXP; e++) acc[e] = fmaf(x, r[e], acc[e]);
    }
    __shared__ float red[NEXP][256];
#pragma unroll
    for (int e = 0; e < NEXP; e++) red[e][tid] = acc[e];
    __syncthreads();
    for (int o = 128; o > 0; o >>= 1) {
        if (tid < o)
#pragma unroll
            for (int e = 0; e < NEXP; e++) red[e][tid] += red[e][tid+o];
        __syncthreads();
    }
    if (tid == 0) {
        float best = red[0][0]; int bi = 0;
#pragma unroll
        for (int e = 1; e < NEXP; e++) if (red[e][0] > best) { best = red[e][0]; bi = e; }
        g_eidx[row] = bi;
        g_gateval[row] = 1.f / (1.f + expf(-best));
        atomicAdd(&g_hist[bi], 1);
    }
}

__global__ void zero8_kernel() {
    int i = threadIdx.x;
    if (i < NEXP) { g_hist[i] = 0; g_ctr[i] = 0; }
}
__global__ void prefix_kernel() {
    if (threadIdx.x == 0) {
        int s = 0;
        for (int e = 0; e < NEXP; e++) { g_seg_start[e] = s; g_seg_count[e] = g_hist[e]; s += g_hist[e]; }
        g_seg_start[NEXP] = s;
    }
}
__global__ void scatter_kernel() {
    int tk = blockIdx.x*256 + threadIdx.x;
    if (tk < NTOK) {
        int e = g_eidx[tk];
        int pos = atomicAdd(&g_ctr[e], 1);
        g_perm[g_seg_start[e] + pos] = tk;
    }
}

__global__ void __launch_bounds__(256) gather_pack(const float* __restrict__ t) {
    int i = blockIdx.x;
    int s = g_perm[i];
    float g = g_gateval[s];
    const float* src = t + (ll)s*DIM;
    for (int d2 = threadIdx.x; d2 < 1024; d2 += 256) {
        float2 v = *reinterpret_cast<const float2*>(src + 2*d2);
        g2_tg[(ll)i*1024 + d2] = hsplit2(v.x*g, v.y*g);
    }
}

__global__ void __launch_bounds__(256) act_pack(const float* __restrict__ gu) {
    ll i2 = (ll)blockIdx.x*256 + threadIdx.x;
    ll row = i2 >> 10, f2 = i2 & 1023;
    const float* r = gu + row*2*FDIM;
    float g0 = r[2*f2], g1 = r[2*f2+1];
    float u0 = r[FDIM + 2*f2], u1 = r[FDIM + 2*f2+1];
    float a0 = u0 * (g0 / (1.f + expf(-g0)));
    float a1 = u1 * (g1 / (1.f + expf(-g1)));
    g2_act[i2] = hsplit2(a0, a1);
}

__global__ void __launch_bounds__(256) swiglu_pack(
    const float* __restrict__ g, const float* __restrict__ u)
{
    ll i2 = (ll)blockIdx.x*256 + threadIdx.x;
    float g0 = g[2*i2], g1 = g[2*i2+1];
    float u0 = u[2*i2], u1 = u[2*i2+1];
    float a0 = u0 * (g0 / (1.f + expf(-g0)));
    float a1 = u1 * (g1 / (1.f + expf(-g1)));
    g2_sg[i2] = hsplit2(a0, a1);
}

__global__ void __launch_bounds__(256) final_add_kernel(
    const float* __restrict__ hs2, const float* __restrict__ shared_,
    const float* __restrict__ routed, float* __restrict__ out)
{
    ll i = (ll)blockIdx.x*256 + threadIdx.x;
    out[i] = hs2[i] + shared_[i] + routed[i];
}

// ----------------------------- launcher ------------------------------------
static void* symp(const void* sym) { void* p = nullptr; cudaGetSymbolAddress(&p, sym); return p; }

extern "C" void kernel_launch(void* const* d_in, const int* in_sizes, int n_in,
                              void* d_out, int out_size)
{
    (void)in_sizes; (void)n_in; (void)out_size;
    const float* hidden = (const float*)d_in[0];
    const float* fcos   = (const float*)d_in[1];
    const float* fsin   = (const float*)d_in[2];
    const float* wq     = (const float*)d_in[5];
    const float* wk     = (const float*)d_in[6];
    const float* wv     = (const float*)d_in[7];
    const float* wo     = (const float*)d_in[8];
    const float* ln1    = (const float*)d_in[9];
    const float* ln2    = (const float*)d_in[10];
    const float* rw     = (const float*)d_in[11];
    const float* gup    = (const float*)d_in[12];
    const float* dwn    = (const float*)d_in[13];
    const float* sgw    = (const float*)d_in[14];
    const float* suw    = (const float*)d_in[15];
    const float* sdw    = (const float*)d_in[16];
    float* out = (float*)d_out;

    float* qb     = (float*)symp(g_q);
    float* kb     = (float*)symp(g_k);
    float* vb     = (float*)symp(g_v);
    float* sc     = (float*)symp(g_scores);
    float* hs2    = (float*)symp(g_hs2);
    float* tb     = (float*)symp(g_t);
    float* gu     = (float*)symp(g_gu);
    float* sg     = (float*)symp(g_sg);
    float* su     = (float*)symp(g_su);
    float* routed = (float*)symp(g_routed);
    float* shd    = (float*)symp(g_shared);
    uint2* hsn2   = (uint2*)symp(g2_hsn);
    uint2* q2     = (uint2*)symp(g2_q);
    uint2* kT2    = (uint2*)symp(g2_kT);
    uint2* v2     = (uint2*)symp(g2_v);
    uint2* P2     = (uint2*)symp(g2_P);
    uint2* attn2  = (uint2*)symp(g2_attn);
    uint2* tb2    = (uint2*)symp(g2_t);
    uint2* tg2    = (uint2*)symp(g2_tg);
    uint2* act2   = (uint2*)symp(g2_act);
    uint2* sg2    = (uint2*)symp(g2_sg);
    uint2* wq2    = (uint2*)symp(g2_wq);
    uint2* wk2    = (uint2*)symp(g2_wk);
    uint2* wv2    = (uint2*)symp(g2_wv);
    uint2* wo2    = (uint2*)symp(g2_wo);
    uint2* sgw2   = (uint2*)symp(g2_sgw);
    uint2* suw2   = (uint2*)symp(g2_suw);
    uint2* sdw2   = (uint2*)symp(g2_sdw);

    cudaFuncSetAttribute(hm_dense,     cudaFuncAttributeMaxDynamicSharedMemorySize, SMEM_BYTES);
    cudaFuncSetAttribute(hm_dense_2t,  cudaFuncAttributeMaxDynamicSharedMemorySize, SMEM_BYTES);
    cudaFuncSetAttribute(hm_dense2,    cudaFuncAttributeMaxDynamicSharedMemorySize, SMEM_BYTES);
    cudaFuncSetAttribute(hm_dense2_2t, cudaFuncAttributeMaxDynamicSharedMemorySize, SMEM_BYTES);
    cudaFuncSetAttribute(hm_qk,        cudaFuncAttributeMaxDynamicSharedMemorySize, SMEM_BYTES);
    cudaFuncSetAttribute(hm_pv,        cudaFuncAttributeMaxDynamicSharedMemorySize, SMEM_BYTES);
    cudaFuncSetAttribute(hm_gateup,    cudaFuncAttributeMaxDynamicSharedMemorySize, SMEM_BYTES);
    cudaFuncSetAttribute(hm_down,      cudaFuncAttributeMaxDynamicSharedMemorySize, SMEM_BYTES);

    // side streams + fork/join events (created once, on the uncaptured
    // correctness call; reused inside graph capture thereafter)
    static cudaStream_t s1 = nullptr, s2 = nullptr;
    static cudaEvent_t  ev0, ev1, ev2, ev3, ev4, ev5;
    if (!s1) {
        cudaStreamCreateWithFlags(&s1, cudaStreamNonBlocking);
        cudaStreamCreateWithFlags(&s2, cudaStreamNonBlocking);
        cudaEventCreateWithFlags(&ev0, cudaEventDisableTiming);
        cudaEventCreateWithFlags(&ev1, cudaEventDisableTiming);
        cudaEventCreateWithFlags(&ev2, cudaEventDisableTiming);
        cudaEventCreateWithFlags(&ev3, cudaEventDisableTiming);
        cudaEventCreateWithFlags(&ev4, cudaEventDisableTiming);
        cudaEventCreateWithFlags(&ev5, cudaEventDisableTiming);
    }

    // 0) early weight conversions (needed by QKV) on main stream
    conv_pb4<<<2048, 256>>>(wq,  wq2,  11);
    conv_pb4<<< 512, 256>>>(wk,  wk2,   9);
    conv_pb4<<< 512, 256>>>(wv,  wv2,   9);
    // fork late weight conversions to s1 (needed only at WO / shared expert)
    cudaEventRecord(ev0, 0);
    cudaStreamWaitEvent(s1, ev0, 0);
    conv_pb4<<<2048, 256, 0, s1>>>(wo,  wo2,  11);
    conv_pb4<<<2048, 256, 0, s1>>>(sgw, sgw2, 11);
    conv_pb4<<<2048, 256, 0, s1>>>(suw, suw2, 11);
    conv_pb4<<<2048, 256, 0, s1>>>(sdw, sdw2, 11);

    // 1) pre-attn RMSNorm (packed only)
    rms_pack<<<NTOK, 256>>>(hidden, ln1, nullptr, hsn2);
    // fork K/V branch to s2 (overlaps wq GEMM + rope_q)
    cudaEventRecord(ev1, 0);
    cudaStreamWaitEvent(s2, ev1, 0);
    hm_dense2<<<dim3(16,8,2), 256, SMEM_BYTES, s2>>>(hsn2, wk2, kb, wv2, vb, NTOK, DIM, 1024, 512, 512);
    rope_pack<1><<<dim3(SQ, NKV), 64, 0, s2>>>(kb, fcos, fsin, kT2, KVD);
    conv_pb4<<<512, 256, 0, s2>>>(vb, v2, 9);
    // main: Q path
    hm_dense<<<dim3(16,32), 256, SMEM_BYTES>>>(hsn2, wq2, qb, nullptr, NTOK, DIM, 1024, 2048, 2048);
    rope_pack<0><<<dim3(SQ, NHEADS), 64>>>(qb, fcos, fsin, q2, DIM);
    // join K/V branch
    cudaEventRecord(ev2, s2);
    cudaStreamWaitEvent(0, ev2, 0);
    // 4) scores = Q K^T (3-term, causal tile skip)
    hm_qk<<<dim3(16,32,NHEADS), 256, SMEM_BYTES>>>(q2, kT2, sc);
    // 5) causal softmax -> packed P2 (single-pass)
    softmax_pack<<<dim3(SQ, NHEADS), 256>>>(sc, P2);
    // 6) attn = P V (3-term, K capped), packed epilogue
    hm_pv<<<dim3(16,2,NHEADS), 256, SMEM_BYTES>>>(P2, v2, attn2);
    // join s1 (wo2/sgw2/suw2/sdw2 ready)
    cudaEventRecord(ev3, s1);
    cudaStreamWaitEvent(0, ev3, 0);
    // 7) output proj + residual (3-term)
    hm_dense<<<dim3(16,32), 256, SMEM_BYTES>>>(attn2, wo2, hs2, hidden, NTOK, DIM, 1024, 2048, 2048);
    // 8) post-attn RMSNorm (fp32 + packed)
    rms_pack<<<NTOK, 256>>>(hs2, ln2, tb, tb2);
    // fork shared expert to s1 (runs concurrently with router + routed MoE)
    cudaEventRecord(ev4, 0);
    cudaStreamWaitEvent(s1, ev4, 0);
    hm_dense2_2t<<<dim3(16,32,2), 256, SMEM_BYTES, s1>>>(tb2, sgw2, sg, suw2, su, NTOK, DIM, 1024, 2048, 2048);
    swiglu_pack<<<(NTOK*1024)/256, 256, 0, s1>>>(sg, su);
    hm_dense_2t<<<dim3(16,32), 256, SMEM_BYTES, s1>>>(sg2, sdw2, shd, nullptr, NTOK, FDIM, 1024, 2048, 2048);
    // main: router + routed expert (2-term, B fp32 hi-only split in-kernel)
    zero8_kernel<<<1, 32>>>();
    router_kernel<<<NTOK, 256>>>(tb, rw);
    prefix_kernel<<<1, 32>>>();
    scatter_kernel<<<8, 256>>>();
    gather_pack<<<NTOK, 256>>>(tb);
    hm_gateup<<<dim3(16,64,NEXP), 256, SMEM_BYTES>>>(tg2, gup, gu);
    act_pack<<<(NTOK*1024)/256, 256>>>(gu);
    hm_down<<<dim3(16,32,NEXP), 256, SMEM_BYTES>>>(act2, dwn, routed);
    // join shared expert
    cudaEventRecord(ev5, s1);
    cudaStreamWaitEvent(0, ev5, 0);
    // 12) final residual + shared + routed
    final_add_kernel<<<(NTOK*DIM)/256, 256>>>(hs2, shd, routed, out);
}

// round 16
// speedup vs baseline: 2.0323x; 1.0094x over previous
#include <cuda_runtime.h>
#include <cuda_bf16.h>
#include <cstdint>
#include <math.h>

typedef long long ll;

#define SQ     2048
#define DIM    2048
#define NHEADS 16
#define NKV    4
#define HDIM   128
#define KVD    512
#define NEXP   8
#define FDIM   2048
#define NTOK   2048

#define BM 128
#define BN 64
#define BK 32
#define LDA2 20
#define LDB2 68
#define SMEM_A_BYTES (BM*LDA2*8)              // 20480
#define SMEM_B_BYTES ((BK/2)*LDB2*8)          // 8704
#define SMEM_BUF     (SMEM_A_BYTES + SMEM_B_BYTES)   // 29184
#define SMEM_BYTES   (2*SMEM_BUF)             // 58368

static const float kScaling = 0.08838834764831845f;  // 128^-0.5

// ----------------------------- scratch (device globals) --------------------
__device__ float g_q     [(ll)NTOK*DIM];
__device__ float g_k     [(ll)NTOK*KVD];
__device__ float g_v     [(ll)NTOK*KVD];
__device__ float g_scores[(ll)NHEADS*SQ*SQ];
__device__ float g_hs2   [(ll)NTOK*DIM];
__device__ float g_t     [(ll)NTOK*DIM];
__device__ float g_gu    [(ll)NTOK*2*FDIM];
__device__ float g_sg    [(ll)NTOK*FDIM];
__device__ float g_su    [(ll)NTOK*FDIM];
__device__ float g_routed[(ll)NTOK*DIM];
__device__ float g_shared[(ll)NTOK*DIM];
// packed split-fp16 (uint2 = {hi_pair, lo_pair} along k)
__device__ uint2 g2_hsn [(ll)NTOK*1024];
__device__ uint2 g2_q   [(ll)NTOK*1024];
__device__ uint2 g2_kT  [(ll)NKV*64*SQ];
__device__ uint2 g2_v   [(ll)1024*KVD];
__device__ uint2 g2_P   [(ll)NHEADS*SQ*1024];
__device__ uint2 g2_attn[(ll)NTOK*1024];
__device__ uint2 g2_t   [(ll)NTOK*1024];
__device__ uint2 g2_tg  [(ll)NTOK*1024];
__device__ uint2 g2_act [(ll)NTOK*1024];
__device__ uint2 g2_sg  [(ll)NTOK*1024];
__device__ uint2 g2_wq  [(ll)1024*2048];
__device__ uint2 g2_wk  [(ll)1024*512];
__device__ uint2 g2_wv  [(ll)1024*512];
__device__ uint2 g2_wo  [(ll)1024*2048];
__device__ uint2 g2_sgw [(ll)1024*2048];
__device__ uint2 g2_suw [(ll)1024*2048];
__device__ uint2 g2_sdw [(ll)1024*2048];
// router state
__device__ int   g_eidx[NTOK];
__device__ float g_gateval[NTOK];
__device__ int   g_hist[NEXP], g_ctr[NEXP], g_seg_start[NEXP+1], g_seg_count[NEXP];
__device__ int   g_perm[NTOK];

// ----------------------------- helpers -------------------------------------
__device__ __forceinline__ uint32_t smem_u32(const void* p) {
    uint32_t a;
    asm("{ .reg .u64 t; cvta.to.shared.u64 t, %1; cvt.u32.u64 %0, t; }" : "=r"(a) : "l"(p));
    return a;
}
// split (x,y) -> {hi_pair, lo_pair}
__device__ __forceinline__ uint2 hsplit2(float x, float y) {
    uint2 r;
    asm("{\n\t"
        ".reg .b16 hx,hy;\n\t"
        ".reg .f32 fx,fy,rx,ry;\n\t"
        "cvt.rn.f16x2.f32 %0, %3, %2;\n\t"
        "mov.b32 {hx,hy}, %0;\n\t"
        "cvt.f32.f16 fx, hx;\n\t"
        "cvt.f32.f16 fy, hy;\n\t"
        "sub.f32 rx, %2, fx;\n\t"
        "sub.f32 ry, %3, fy;\n\t"
        "cvt.rn.f16x2.f32 %1, ry, rx;\n\t"
        "}" : "=r"(r.x), "=r"(r.y) : "f"(x), "f"(y));
    return r;
}
// hi-only pack (for 2-term B): one packed convert
__device__ __forceinline__ uint32_t hpack2(float x, float y) {
    uint32_t r;
    asm("cvt.rn.f16x2.f32 %0, %2, %1;" : "=r"(r) : "f"(x), "f"(y));
    return r;
}
__device__ __forceinline__ void mma_f16(float* c, uint32_t a0, uint32_t a1, uint32_t a2, uint32_t a3,
                                        uint32_t b0, uint32_t b1) {
    asm volatile("mma.sync.aligned.m16n8k16.row.col.f32.f16.f16.f32 "
        "{%0,%1,%2,%3}, {%4,%5,%6,%7}, {%8,%9}, {%0,%1,%2,%3};"
        : "+f"(c[0]), "+f"(c[1]), "+f"(c[2]), "+f"(c[3])
        : "r"(a0), "r"(a1), "r"(a2), "r"(a3), "r"(b0), "r"(b1));
}
__device__ __forceinline__ void cpa16(uint32_t dst, const void* src, int szbytes) {
    asm volatile("cp.async.cg.shared.global [%0], [%1], 16, %2;"
        :: "r"(dst), "l"(src), "r"(szbytes));
}

// ----------------------------- GEMM tile copy helpers -----------------------
__device__ __forceinline__ void issue_A(
    uint32_t sa, const uint2* __restrict__ A,
    int M, int lda2, int m0, int jbase, int tid)
{
#pragma unroll
    for (int i = 0; i < 4; i++) {
        int chunk = tid + (i << 8);
        int row = chunk >> 3, sp = (chunk & 7) << 1;
        int gm = m0 + row;
        int ok = (gm < M) ? 16 : 0;
        const uint2* src = A + (ll)min(gm, M - 1)*lda2 + jbase + sp;
        cpa16(sa + (uint32_t)(row*LDA2 + sp)*8u, src, ok);
    }
}
__device__ __forceinline__ void issue_B(
    uint32_t sb, const uint2* __restrict__ B,
    int ldbN, int n0, int jbase, int tid)
{
#pragma unroll
    for (int i = 0; i < 2; i++) {
        int chunk = tid + (i << 8);
        int jr = chunk >> 5, nq = (chunk & 31) << 1;
        const uint2* src = B + (ll)(jbase + jr)*ldbN + n0 + nq;
        cpa16(sb + (uint32_t)(jr*LDB2 + nq)*8u, src, 16);
    }
}

// ----------------------------- tensor GEMM body -----------------------------
// NT=3: Ah*Bh + Ah*Bl + Al*Bh (full split). NT=2: Ah*Bh + Al*Bh (A full x B hi).
template<bool KCAP, bool RM, bool PACKC, bool BF32, int NT>
__device__ __forceinline__ void hm_body(
    const uint2* __restrict__ A, const void* __restrict__ Bv,
    void* __restrict__ Cv, const float* __restrict__ Cadd,
    int M, int K, int lda2, int ldbN, int ldc, int m0, int n0,
    const int* __restrict__ rowmap)
{
    extern __shared__ char smem[];
    const uint32_t sbase = smem_u32(smem);

    const int tid = threadIdx.x;
    const int wid = tid >> 5, lid = tid & 31;
    const int wm = (wid & 3) << 5;
    const int wn = (wid >> 2) << 5;
    const int lr = lid >> 2;
    const int ca = lid & 3;
    const int lc = ca << 1;

    const float* Bf = reinterpret_cast<const float*>(Bv);
    const uint2* Bp = reinterpret_cast<const uint2*>(Bv);
    const int b_kr2 = tid >> 4;
    const int b_n4  = (tid & 15) << 2;
    float4 vb0, vb1;

    float acc[2][4][4];
#pragma unroll
    for (int i = 0; i < 2; i++)
#pragma unroll
        for (int j = 0; j < 4; j++)
#pragma unroll
            for (int q = 0; q < 4; q++) acc[i][j][q] = 0.f;

    int Keff = K;
    if (KCAP) Keff = min(K, m0 + BM);
    const int nch = Keff >> 5;

    issue_A(sbase, A, M, lda2, m0, 0, tid);
    if (!BF32) issue_B(sbase + SMEM_A_BYTES, Bp, ldbN, n0, 0, tid);
    asm volatile("cp.async.commit_group;" ::: "memory");
    if (BF32) {
        const float* bp = Bf + (ll)(2*b_kr2)*ldbN + n0 + b_n4;
        vb0 = *reinterpret_cast<const float4*>(bp);
        vb1 = *reinterpret_cast<const float4*>(bp + ldbN);
    }

    for (int c = 0; c < nch; c++) {
        const int cur = c & 1;
        if (BF32) {
            uint2* Bsw = reinterpret_cast<uint2*>(smem + cur*SMEM_BUF + SMEM_A_BYTES);
            if (NT == 3) {
                Bsw[b_kr2*LDB2 + b_n4 + 0] = hsplit2(vb0.x, vb1.x);
                Bsw[b_kr2*LDB2 + b_n4 + 1] = hsplit2(vb0.y, vb1.y);
                Bsw[b_kr2*LDB2 + b_n4 + 2] = hsplit2(vb0.z, vb1.z);
                Bsw[b_kr2*LDB2 + b_n4 + 3] = hsplit2(vb0.w, vb1.w);
            } else {
                Bsw[b_kr2*LDB2 + b_n4 + 0] = make_uint2(hpack2(vb0.x, vb1.x), 0u);
                Bsw[b_kr2*LDB2 + b_n4 + 1] = make_uint2(hpack2(vb0.y, vb1.y), 0u);
                Bsw[b_kr2*LDB2 + b_n4 + 2] = make_uint2(hpack2(vb0.z, vb1.z), 0u);
                Bsw[b_kr2*LDB2 + b_n4 + 3] = make_uint2(hpack2(vb0.w, vb1.w), 0u);
            }
        }
        if (c + 1 < nch) {
            uint32_t nb = sbase + (uint32_t)(cur ^ 1)*SMEM_BUF;
            issue_A(nb, A, M, lda2, m0, (c + 1) << 4, tid);
            if (!BF32) issue_B(nb + SMEM_A_BYTES, Bp, ldbN, n0, (c + 1) << 4, tid);
            asm volatile("cp.async.commit_group;" ::: "memory");
            if (BF32) {
                const float* bp = Bf + (ll)(((c + 1) << 5) + 2*b_kr2)*ldbN + n0 + b_n4;
                vb0 = *reinterpret_cast<const float4*>(bp);
                vb1 = *reinterpret_cast<const float4*>(bp + ldbN);
            }
            asm volatile("cp.async.wait_group 1;" ::: "memory");
        } else {
            asm volatile("cp.async.wait_group 0;" ::: "memory");
        }
        __syncthreads();

        const uint2* As = reinterpret_cast<const uint2*>(smem + cur*SMEM_BUF);
        const uint2* Bs = reinterpret_cast<const uint2*>(smem + cur*SMEM_BUF + SMEM_A_BYTES);

#pragma unroll
        for (int s = 0; s < 2; s++) {
            const int jb = s << 3;
            uint2 bfr[4][2];
#pragma unroll
            for (int nt = 0; nt < 4; nt++) {
                int n = wn + nt*8 + lr;
                bfr[nt][0] = Bs[(jb + ca    )*LDB2 + n];
                bfr[nt][1] = Bs[(jb + ca + 4)*LDB2 + n];
            }
#pragma unroll
            for (int mt = 0; mt < 2; mt++) {
                int r = wm + mt*16 + lr;
                uint2 a0 = As[ r     *LDA2 + jb + ca    ];
                uint2 a1 = As[(r + 8)*LDA2 + jb + ca    ];
                uint2 a2 = As[ r     *LDA2 + jb + ca + 4];
                uint2 a3 = As[(r + 8)*LDA2 + jb + ca + 4];
#pragma unroll
                for (int nt = 0; nt < 4; nt++) {
                    mma_f16(acc[mt][nt], a0.x, a1.x, a2.x, a3.x, bfr[nt][0].x, bfr[nt][1].x);
                    if (NT == 3)
                        mma_f16(acc[mt][nt], a0.x, a1.x, a2.x, a3.x, bfr[nt][0].y, bfr[nt][1].y);
                    mma_f16(acc[mt][nt], a0.y, a1.y, a2.y, a3.y, bfr[nt][0].x, bfr[nt][1].x);
                }
            }
        }
        __syncthreads();
    }

#pragma unroll
    for (int mt = 0; mt < 2; mt++) {
        int mbase = m0 + wm + mt*16 + lr;
#pragma unroll
        for (int half = 0; half < 2; half++) {
            int m = mbase + half*8;
            if (m < M) {
                int srow = RM ? rowmap[m] : m;
#pragma unroll
                for (int nt = 0; nt < 4; nt++) {
                    int n = n0 + wn + nt*8 + lc;
                    float2 v = half ? make_float2(acc[mt][nt][2], acc[mt][nt][3])
                                    : make_float2(acc[mt][nt][0], acc[mt][nt][1]);
                    if (PACKC) {
                        uint2* C2 = reinterpret_cast<uint2*>(Cv);
                        C2[(ll)srow*(ldc >> 1) + (n >> 1)] = hsplit2(v.x, v.y);
                    } else {
                        float* C = reinterpret_cast<float*>(Cv);
                        if (Cadd) {
                            float2 a = *reinterpret_cast<const float2*>(Cadd + (ll)m*ldc + n);
                            v.x += a.x; v.y += a.y;
                        }
                        *reinterpret_cast<float2*>(C + (ll)srow*ldc + n) = v;
                    }
                }
            }
        }
    }
}

// ----------------------------- GEMM wrappers -------------------------------
__global__ void __launch_bounds__(256, 3) hm_dense(
    const uint2* __restrict__ A, const uint2* __restrict__ B,
    float* __restrict__ C, const float* __restrict__ Cadd,
    int M, int K, int lda2, int ldbN, int ldc)
{
    hm_body<false, false, false, false, 3>(A, B, C, Cadd, M, K, lda2, ldbN, ldc,
                                           blockIdx.x << 7, blockIdx.y << 6, nullptr);
}

// 2-term dense (sdw)
__global__ void __launch_bounds__(256, 3) hm_dense_2t(
    const uint2* __restrict__ A, const uint2* __restrict__ B,
    float* __restrict__ C, const float* __restrict__ Cadd,
    int M, int K, int lda2, int ldbN, int ldc)
{
    hm_body<false, false, false, false, 2>(A, B, C, Cadd, M, K, lda2, ldbN, ldc,
                                           blockIdx.x << 7, blockIdx.y << 6, nullptr);
}

__global__ void __launch_bounds__(256, 3) hm_dense2(
    const uint2* __restrict__ A,
    const uint2* __restrict__ B0, float* __restrict__ C0,
    const uint2* __restrict__ B1, float* __restrict__ C1,
    int M, int K, int lda2, int ldbN, int ldc)
{
    const uint2* B = blockIdx.z ? B1 : B0;
    float* C = blockIdx.z ? C1 : C0;
    hm_body<false, false, false, false, 3>(A, B, C, nullptr, M, K, lda2, ldbN, ldc,
                                           blockIdx.x << 7, blockIdx.y << 6, nullptr);
}

// 2-term paired dense (shared-expert sg/su)
__global__ void __launch_bounds__(256, 3) hm_dense2_2t(
    const uint2* __restrict__ A,
    const uint2* __restrict__ B0, float* __restrict__ C0,
    const uint2* __restrict__ B1, float* __restrict__ C1,
    int M, int K, int lda2, int ldbN, int ldc)
{
    const uint2* B = blockIdx.z ? B1 : B0;
    float* C = blockIdx.z ? C1 : C0;
    hm_body<false, false, false, false, 2>(A, B, C, nullptr, M, K, lda2, ldbN, ldc,
                                           blockIdx.x << 7, blockIdx.y << 6, nullptr);
}

// attention GEMMs take pre-offset base pointers; blockIdx.z = head within half
__global__ void __launch_bounds__(256, 3) hm_qk(
    const uint2* __restrict__ q2, const uint2* __restrict__ kT2, float* __restrict__ scv)
{
    int h = blockIdx.z;
    int m0 = blockIdx.x << 7, n0 = blockIdx.y << 6;
    if (n0 > m0 + (BM - 1)) return;
    hm_body<false, false, false, false, 3>(q2 + h*64, kT2 + (ll)(h >> 2)*64*SQ,
                                           scv + (ll)h*SQ*SQ, nullptr,
                                           SQ, HDIM, 1024, SQ, SQ, m0, n0, nullptr);
}

__global__ void __launch_bounds__(256, 3) hm_pv(
    const uint2* __restrict__ P2, const uint2* __restrict__ v2, uint2* __restrict__ attn2)
{
    int h = blockIdx.z;
    hm_body<true, false, true, false, 3>(P2 + (ll)h*SQ*1024, v2 + (h >> 2)*HDIM,
                                         attn2 + h*(HDIM/2), nullptr,
                                         SQ, SQ, 1024, KVD, DIM, blockIdx.x << 7, blockIdx.y << 6, nullptr);
}

__global__ void __launch_bounds__(256, 2) hm_gateup(
    const uint2* __restrict__ tg2, const float* __restrict__ gup, float* __restrict__ gu)
{
    int e = blockIdx.z;
    int cnt = g_seg_count[e];
    int m0 = blockIdx.x << 7;
    if (m0 >= cnt) return;
    int st = g_seg_start[e];
    hm_body<false, false, false, true, 2>(tg2 + (ll)st*1024, gup + (ll)e*DIM*2*FDIM,
                                          gu + (ll)st*2*FDIM, nullptr,
                                          cnt, DIM, 1024, 2*FDIM, 2*FDIM, m0, blockIdx.y << 6, nullptr);
}

__global__ void __launch_bounds__(256, 2) hm_down(
    const uint2* __restrict__ act2, const float* __restrict__ dwn, float* __restrict__ outr)
{
    int e = blockIdx.z;
    int cnt = g_seg_count[e];
    int m0 = blockIdx.x << 7;
    if (m0 >= cnt) return;
    int st = g_seg_start[e];
    hm_body<false, true, false, true, 2>(act2 + (ll)st*1024, dwn + (ll)e*FDIM*DIM,
                                         outr, nullptr,
                                         cnt, FDIM, 1024, DIM, DIM, m0, blockIdx.y << 6, g_perm + st);
}

// ----------------------------- packers / converters -------------------------
__global__ void __launch_bounds__(256) conv_pb4(
    const float* __restrict__ src, uint2* __restrict__ dst, int nlog)
{
    ll i = ((ll)blockIdx.x*256 + threadIdx.x) << 2;
    ll n = i & ((1 << nlog) - 1);
    ll j = i >> nlog;
    const float4 x = *reinterpret_cast<const float4*>(src + ((j << 1)      << nlog) + n);
    const float4 y = *reinterpret_cast<const float4*>(src + (((j << 1)|1)  << nlog) + n);
    uint2 d0 = hsplit2(x.x, y.x);
    uint2 d1 = hsplit2(x.y, y.y);
    uint2 d2 = hsplit2(x.z, y.z);
    uint2 d3 = hsplit2(x.w, y.w);
    uint4* o = reinterpret_cast<uint4*>(dst + i);
    o[0] = make_uint4(d0.x, d0.y, d1.x, d1.y);
    o[1] = make_uint4(d2.x, d2.y, d3.x, d3.y);
}

__global__ void __launch_bounds__(256) rms_pack(
    const float* __restrict__ x, const float* __restrict__ w,
    float* __restrict__ y, uint2* __restrict__ y2)
{
    int row = blockIdx.x, tid = threadIdx.x;
    const float* xr = x + (ll)row*DIM;
    float s = 0.f;
    for (int d = tid; d < DIM; d += 256) { float v = xr[d]; s = fmaf(v, v, s); }
    __shared__ float red[256];
    red[tid] = s; __syncthreads();
    for (int o = 128; o > 0; o >>= 1) { if (tid < o) red[tid] += red[tid+o]; __syncthreads(); }
    float inv = rsqrtf(red[0] * (1.0f/DIM) + 1e-5f);
    for (int d2 = tid; d2 < 1024; d2 += 256) {
        float2 v = *reinterpret_cast<const float2*>(xr + 2*d2);
        float a = v.x * inv * w[2*d2];
        float b = v.y * inv * w[2*d2+1];
        if (y) *reinterpret_cast<float2*>(y + (ll)row*DIM + 2*d2) = make_float2(a, b);
        y2[(ll)row*1024 + d2] = hsplit2(a, b);
    }
}

template<int KM>
__global__ void rope_pack(const float* __restrict__ in, const float* __restrict__ cosb,
                          const float* __restrict__ sinb, uint2* __restrict__ out, int ld)
{
    int s = blockIdx.x, h = blockIdx.y, j = threadIdx.x;  // j: 0..63
    const float* p = in + (ll)s*ld + h*HDIM;
    float a = p[2*j], b = p[2*j+1];
    float c  = cosb[s*64 + j];
    float sn = sinb[s*64 + j];
    float na = a*c - b*sn;
    float nb = a*sn + b*c;
    __shared__ float red[64];
    red[j] = na*na + nb*nb; __syncthreads();
    for (int o = 32; o > 0; o >>= 1) { if (j < o) red[j] += red[j+o]; __syncthreads(); }
    float scale = rsqrtf(red[0] * (1.0f/HDIM) + 1e-6f);
    na *= scale; nb *= scale;
    if (KM == 0)
        out[(ll)s*1024 + h*64 + j] = hsplit2(na, nb);
    else
        out[(ll)(h*64 + j)*SQ + s] = hsplit2(na, nb);
}

// causal softmax -> packed PA P2; single global read pass (rows cached in regs)
__global__ void __launch_bounds__(256) softmax_pack(
    const float* __restrict__ scores, uint2* __restrict__ P2)
{
    int row = blockIdx.x, h = blockIdx.y, tid = threadIdx.x;
    const float* p = scores + ((ll)h*SQ + row)*SQ;
    uint2* o = P2 + ((ll)h*SQ + row)*1024;
    int n = row + 1;
    int np = (n + 1) >> 1;
    int zend2 = ((row >> 7) << 6) + 64;
    __shared__ float red[256];

    float2 xv[4];
    float mx = -1e30f;
#pragma unroll
    for (int k = 0; k < 4; k++) {
        int j2 = tid + (k << 8);
        float2 v = make_float2(-1e30f, -1e30f);
        if (j2 < np) {
            v = *reinterpret_cast<const float2*>(p + 2*j2);
            v.x *= kScaling;
            v.y = (2*j2 + 1 < n) ? v.y * kScaling : -1e30f;
        }
        xv[k] = v;
        mx = fmaxf(mx, fmaxf(v.x, v.y));
    }
    red[tid] = mx; __syncthreads();
    for (int q = 128; q > 0; q >>= 1) { if (tid < q) red[tid] = fmaxf(red[tid], red[tid+q]); __syncthreads(); }
    mx = red[0]; __syncthreads();

    float sum = 0.f;
#pragma unroll
    for (int k = 0; k < 4; k++) {
        int j2 = tid + (k << 8);
        float e0 = expf(xv[k].x - mx);
        float e1 = expf(xv[k].y - mx);
        xv[k] = make_float2(e0, e1);
        if (j2 < np) sum += e0 + e1;
    }
    red[tid] = sum; __syncthreads();
    for (int q = 128; q > 0; q >>= 1) { if (tid < q) red[tid] += red[tid+q]; __syncthreads(); }
    float inv = 1.f / red[0];

#pragma unroll
    for (int k = 0; k < 4; k++) {
        int j2 = tid + (k << 8);
        if (j2 < np) o[j2] = hsplit2(xv[k].x*inv, xv[k].y*inv);
    }
    for (int j2 = np + tid; j2 < zend2; j2 += 256) o[j2] = make_uint2(0u, 0u);
}

__global__ void __launch_bounds__(256) router_kernel(
    const float* __restrict__ t, const float* __restrict__ rw)
{
    int row = blockIdx.x, tid = threadIdx.x;
    float acc[NEXP] = {};
    const float* xr = t + (ll)row*DIM;
    for (int d = tid; d < DIM; d += 256) {
        float x = xr[d];
        const float* r = rw + d*NEXP;
#pragma unroll
        for (int e = 0; e < NEXP; e++) acc[e] = fmaf(x, r[e], acc[e]);
    }
    __shared__ float red[NEXP][256];
#pragma unroll
    for (int e = 0; e < NEXP; e++) red[e][tid] = acc[e];
    __syncthreads();
    for (int o = 128; o > 0; o >>= 1) {
        if (tid < o)
#pragma unroll
            for (int e = 0; e < NEXP; e++) red[e][tid] += red[e][tid+o];
        __syncthreads();
    }
    if (tid == 0) {
        float best = red[0][0]; int bi = 0;
#pragma unroll
        for (int e = 1; e < NEXP; e++) if (red[e][0] > best) { best = red[e][0]; bi = e; }
        g_eidx[row] = bi;
        g_gateval[row] = 1.f / (1.f + expf(-best));
        atomicAdd(&g_hist[bi], 1);
    }
}

__global__ void zero8_kernel() {
    int i = threadIdx.x;
    if (i < NEXP) { g_hist[i] = 0; g_ctr[i] = 0; }
}
__global__ void prefix_kernel() {
    if (threadIdx.x == 0) {
        int s = 0;
        for (int e = 0; e < NEXP; e++) { g_seg_start[e] = s; g_seg_count[e] = g_hist[e]; s += g_hist[e]; }
        g_seg_start[NEXP] = s;
    }
}
__global__ void scatter_kernel() {
    int tk = blockIdx.x*256 + threadIdx.x;
    if (tk < NTOK) {
        int e = g_eidx[tk];
        int pos = atomicAdd(&g_ctr[e], 1);
        g_perm[g_seg_start[e] + pos] = tk;
    }
}

__global__ void __launch_bounds__(256) gather_pack(const float* __restrict__ t) {
    int i = blockIdx.x;
    int s = g_perm[i];
    float g = g_gateval[s];
    const float* src = t + (ll)s*DIM;
    for (int d2 = threadIdx.x; d2 < 1024; d2 += 256) {
        float2 v = *reinterpret_cast<const float2*>(src + 2*d2);
        g2_tg[(ll)i*1024 + d2] = hsplit2(v.x*g, v.y*g);
    }
}

__global__ void __launch_bounds__(256) act_pack(const float* __restrict__ gu) {
    ll i2 = (ll)blockIdx.x*256 + threadIdx.x;
    ll row = i2 >> 10, f2 = i2 & 1023;
    const float* r = gu + row*2*FDIM;
    float g0 = r[2*f2], g1 = r[2*f2+1];
    float u0 = r[FDIM + 2*f2], u1 = r[FDIM + 2*f2+1];
    float a0 = u0 * (g0 / (1.f + expf(-g0)));
    float a1 = u1 * (g1 / (1.f + expf(-g1)));
    g2_act[i2] = hsplit2(a0, a1);
}

__global__ void __launch_bounds__(256) swiglu_pack(
    const float* __restrict__ g, const float* __restrict__ u)
{
    ll i2 = (ll)blockIdx.x*256 + threadIdx.x;
    float g0 = g[2*i2], g1 = g[2*i2+1];
    float u0 = u[2*i2], u1 = u[2*i2+1];
    float a0 = u0 * (g0 / (1.f + expf(-g0)));
    float a1 = u1 * (g1 / (1.f + expf(-g1)));
    g2_sg[i2] = hsplit2(a0, a1);
}

__global__ void __launch_bounds__(256) final_add_kernel(
    const float* __restrict__ hs2, const float* __restrict__ shared_,
    const float* __restrict__ routed, float* __restrict__ out)
{
    ll i = (ll)blockIdx.x*256 + threadIdx.x;
    out[i] = hs2[i] + shared_[i] + routed[i];
}

// ----------------------------- launcher ------------------------------------
static void* symp(const void* sym) { void* p = nullptr; cudaGetSymbolAddress(&p, sym); return p; }

extern "C" void kernel_launch(void* const* d_in, const int* in_sizes, int n_in,
                              void* d_out, int out_size)
{
    (void)in_sizes; (void)n_in; (void)out_size;
    const float* hidden = (const float*)d_in[0];
    const float* fcos   = (const float*)d_in[1];
    const float* fsin   = (const float*)d_in[2];
    const float* wq     = (const float*)d_in[5];
    const float* wk     = (const float*)d_in[6];
    const float* wv     = (const float*)d_in[7];
    const float* wo     = (const float*)d_in[8];
    const float* ln1    = (const float*)d_in[9];
    const float* ln2    = (const float*)d_in[10];
    const float* rw     = (const float*)d_in[11];
    const float* gup    = (const float*)d_in[12];
    const float* dwn    = (const float*)d_in[13];
    const float* sgw    = (const float*)d_in[14];
    const float* suw    = (const float*)d_in[15];
    const float* sdw    = (const float*)d_in[16];
    float* out = (float*)d_out;

    float* qb     = (float*)symp(g_q);
    float* kb     = (float*)symp(g_k);
    float* vb     = (float*)symp(g_v);
    float* sc     = (float*)symp(g_scores);
    float* hs2    = (float*)symp(g_hs2);
    float* tb     = (float*)symp(g_t);
    float* gu     = (float*)symp(g_gu);
    float* sg     = (float*)symp(g_sg);
    float* su     = (float*)symp(g_su);
    float* routed = (float*)symp(g_routed);
    float* shd    = (float*)symp(g_shared);
    uint2* hsn2   = (uint2*)symp(g2_hsn);
    uint2* q2     = (uint2*)symp(g2_q);
    uint2* kT2    = (uint2*)symp(g2_kT);
    uint2* v2     = (uint2*)symp(g2_v);
    uint2* P2     = (uint2*)symp(g2_P);
    uint2* attn2  = (uint2*)symp(g2_attn);
    uint2* tb2    = (uint2*)symp(g2_t);
    uint2* tg2    = (uint2*)symp(g2_tg);
    uint2* act2   = (uint2*)symp(g2_act);
    uint2* sg2    = (uint2*)symp(g2_sg);
    uint2* wq2    = (uint2*)symp(g2_wq);
    uint2* wk2    = (uint2*)symp(g2_wk);
    uint2* wv2    = (uint2*)symp(g2_wv);
    uint2* wo2    = (uint2*)symp(g2_wo);
    uint2* sgw2   = (uint2*)symp(g2_sgw);
    uint2* suw2   = (uint2*)symp(g2_suw);
    uint2* sdw2   = (uint2*)symp(g2_sdw);

    cudaFuncSetAttribute(hm_dense,     cudaFuncAttributeMaxDynamicSharedMemorySize, SMEM_BYTES);
    cudaFuncSetAttribute(hm_dense_2t,  cudaFuncAttributeMaxDynamicSharedMemorySize, SMEM_BYTES);
    cudaFuncSetAttribute(hm_dense2,    cudaFuncAttributeMaxDynamicSharedMemorySize, SMEM_BYTES);
    cudaFuncSetAttribute(hm_dense2_2t, cudaFuncAttributeMaxDynamicSharedMemorySize, SMEM_BYTES);
    cudaFuncSetAttribute(hm_qk,        cudaFuncAttributeMaxDynamicSharedMemorySize, SMEM_BYTES);
    cudaFuncSetAttribute(hm_pv,        cudaFuncAttributeMaxDynamicSharedMemorySize, SMEM_BYTES);
    cudaFuncSetAttribute(hm_gateup,    cudaFuncAttributeMaxDynamicSharedMemorySize, SMEM_BYTES);
    cudaFuncSetAttribute(hm_down,      cudaFuncAttributeMaxDynamicSharedMemorySize, SMEM_BYTES);

    static cudaStream_t s1 = nullptr, s2 = nullptr;
    static cudaEvent_t  ev0, ev1, ev2, ev3, ev4, ev5, ev6;
    if (!s1) {
        cudaStreamCreateWithFlags(&s1, cudaStreamNonBlocking);
        cudaStreamCreateWithFlags(&s2, cudaStreamNonBlocking);
        cudaEventCreateWithFlags(&ev0, cudaEventDisableTiming);
        cudaEventCreateWithFlags(&ev1, cudaEventDisableTiming);
        cudaEventCreateWithFlags(&ev2, cudaEventDisableTiming);
        cudaEventCreateWithFlags(&ev3, cudaEventDisableTiming);
        cudaEventCreateWithFlags(&ev4, cudaEventDisableTiming);
        cudaEventCreateWithFlags(&ev5, cudaEventDisableTiming);
        cudaEventCreateWithFlags(&ev6, cudaEventDisableTiming);
    }

    // 1) pre-attn RMSNorm first (convs overlap it on side streams)
    rms_pack<<<NTOK, 256>>>(hidden, ln1, nullptr, hsn2);
    cudaEventRecord(ev0, 0);
    // s1: late weight conversions (needed at WO / shared expert)
    cudaStreamWaitEvent(s1, ev0, 0);
    conv_pb4<<<2048, 256, 0, s1>>>(wo,  wo2,  11);
    conv_pb4<<<2048, 256, 0, s1>>>(sgw, sgw2, 11);
    conv_pb4<<<2048, 256, 0, s1>>>(suw, suw2, 11);
    conv_pb4<<<2048, 256, 0, s1>>>(sdw, sdw2, 11);
    // s2: K/V branch (conv wk/wv + GEMM + rope_k + v2 pack)
    cudaStreamWaitEvent(s2, ev0, 0);
    conv_pb4<<<512, 256, 0, s2>>>(wk, wk2, 9);
    conv_pb4<<<512, 256, 0, s2>>>(wv, wv2, 9);
    hm_dense2<<<dim3(16,8,2), 256, SMEM_BYTES, s2>>>(hsn2, wk2, kb, wv2, vb, NTOK, DIM, 1024, 512, 512);
    rope_pack<1><<<dim3(SQ, NKV), 64, 0, s2>>>(kb, fcos, fsin, kT2, KVD);
    conv_pb4<<<512, 256, 0, s2>>>(vb, v2, 9);
    cudaEventRecord(ev2, s2);         // K/V ready
    // main: Q path
    conv_pb4<<<2048, 256>>>(wq, wq2, 11);
    hm_dense<<<dim3(16,32), 256, SMEM_BYTES>>>(hsn2, wq2, qb, nullptr, NTOK, DIM, 1024, 2048, 2048);
    rope_pack<0><<<dim3(SQ, NHEADS), 64>>>(qb, fcos, fsin, q2, DIM);
    cudaEventRecord(ev1, 0);          // Q ready

    // 4-6) attention, split by head halves across main and s2
    // main: heads 0-7 (needs K/V from s2)
    cudaStreamWaitEvent(0, ev2, 0);
    hm_qk<<<dim3(16,32,8), 256, SMEM_BYTES>>>(q2, kT2, sc);
    softmax_pack<<<dim3(SQ, 8), 256>>>(sc, P2);
    hm_pv<<<dim3(16,2,8), 256, SMEM_BYTES>>>(P2, v2, attn2);
    // s2: heads 8-15 (needs Q from main)
    cudaStreamWaitEvent(s2, ev1, 0);
    hm_qk<<<dim3(16,32,8), 256, SMEM_BYTES, s2>>>(q2 + 8*64, kT2 + (ll)2*64*SQ, sc + (ll)8*SQ*SQ);
    softmax_pack<<<dim3(SQ, 8), 256, 0, s2>>>(sc + (ll)8*SQ*SQ, P2 + (ll)8*SQ*1024);
    hm_pv<<<dim3(16,2,8), 256, SMEM_BYTES, s2>>>(P2 + (ll)8*SQ*1024, v2 + 2*HDIM, attn2 + 8*(HDIM/2));
    cudaEventRecord(ev6, s2);
    cudaStreamWaitEvent(0, ev6, 0);
    // join s1 (wo2/sgw2/suw2/sdw2 ready)
    cudaEventRecord(ev3, s1);
    cudaStreamWaitEvent(0, ev3, 0);
    // 7) output proj + residual (3-term)
    hm_dense<<<dim3(16,32), 256, SMEM_BYTES>>>(attn2, wo2, hs2, hidden, NTOK, DIM, 1024, 2048, 2048);
    // 8) post-attn RMSNorm (fp32 + packed)
    rms_pack<<<NTOK, 256>>>(hs2, ln2, tb, tb2);
    // fork shared expert to s1 (runs concurrently with router + routed MoE)
    cudaEventRecord(ev4, 0);
    cudaStreamWaitEvent(s1, ev4, 0);
    hm_dense2_2t<<<dim3(16,32,2), 256, SMEM_BYTES, s1>>>(tb2, sgw2, sg, suw2, su, NTOK, DIM, 1024, 2048, 2048);
    swiglu_pack<<<(NTOK*1024)/256, 256, 0, s1>>>(sg, su);
    hm_dense_2t<<<dim3(16,32), 256, SMEM_BYTES, s1>>>(sg2, sdw2, shd, nullptr, NTOK, FDIM, 1024, 2048, 2048);
    // main: router + routed expert (2-term, B fp32 hi-only split in-kernel)
    zero8_kernel<<<1, 32>>>();
    router_kernel<<<NTOK, 256>>>(tb, rw);
    prefix_kernel<<<1, 32>>>();
    scatter_kernel<<<8, 256>>>();
    gather_pack<<<NTOK, 256>>>(tb);
    hm_gateup<<<dim3(16,64,NEXP), 256, SMEM_BYTES>>>(tg2, gup, gu);
    act_pack<<<(NTOK*1024)/256, 256>>>(gu);
    hm_down<<<dim3(16,32,NEXP), 256, SMEM_BYTES>>>(act2, dwn, routed);
    // join shared expert
    cudaEventRecord(ev5, s1);
    cudaStreamWaitEvent(0, ev5, 0);
    // 12) final residual + shared + routed
    final_add_kernel<<<(NTOK*DIM)/256, 256>>>(hs2, shd, routed, out);
}